// round 5
// baseline (speedup 1.0000x reference)
#include <cuda_runtime.h>
#include <math.h>

#define Hc 128
#define Wc 128
#define HWc 16384

typedef unsigned long long u64p;

__device__ __forceinline__ u64p pk(float lo, float hi) {
  u64p r; asm("mov.b64 %0, {%1,%2};" : "=l"(r) : "f"(lo), "f"(hi)); return r;
}
__device__ __forceinline__ void fma2(u64p& a, u64p x, u64p y) {
  asm("fma.rn.f32x2 %0, %1, %2, %0;" : "+l"(a) : "l"(x), "l"(y));
}
__device__ __forceinline__ void fma2b(u64p& a, u64p x, u64p c) {
  asm("fma.rn.f32x2 %0, %0, %1, %2;" : "+l"(a) : "l"(x), "l"(c));
}
__device__ __forceinline__ float2 up(u64p v) {
  float2 f; asm("mov.b64 {%0,%1}, %2;" : "=f"(f.x), "=f"(f.y) : "l"(v)); return f;
}

// activations scratch
__device__ float g_x1[2*64*HWc];
__device__ float g_f [2*32*HWc];
__device__ float g_zp[2*2*HWc];
__device__ float g_x2[2*64*HWc];
__device__ float g_h [2*32*HWc];
// transposed weights ([k][oc] layouts, oc contiguous for packed-pair LDG)
__device__ float g_w1t [128*64];
__device__ float g_wrt [64*32];
__device__ float g_w2t [64*128];
__device__ float g_wp2t[32*128];
__device__ float g_wp1t[288*32];

// ---------------------------------------------------------------------------
__global__ void k_prep(const float* __restrict__ w1, const float* __restrict__ wr,
                       const float* __restrict__ w2, const float* __restrict__ wp2,
                       const float* __restrict__ wp1)
{
  int i = blockIdx.x*256 + threadIdx.x;
  int n = gridDim.x*256;
  for (int k = i; k < 8192; k += n) { int c = k>>6, o = k&63;  g_w1t[k]  = w1[o*128 + c]; }
  for (int k = i; k < 2048; k += n) { int c = k>>5, o = k&31;  g_wrt[k]  = wr[o*64 + c]; }
  for (int k = i; k < 8192; k += n) { int c = k>>7, o = k&127; g_w2t[k]  = w2[o*64 + c]; }
  for (int k = i; k < 4096; k += n) { int c = k>>7, o = k&127; g_wp2t[k] = wp2[o*32 + c]; }
  for (int k = i; k < 9216; k += n) { int tc = k>>5, o = k&31; g_wp1t[k] = wp1[o*288 + tc]; }
}

// ---------------------------------------------------------------------------
// K1: half-row (64 px). conv1 (128->64)+PReLU -> x1; reduce (64->32)+ReLU -> f;
// ZPool -> zp. Weights via broadcast LDG (L1), oc-packed f32x2.
// ---------------------------------------------------------------------------
__global__ __launch_bounds__(256, 3) void k_front(
    const float* __restrict__ x,  const float* __restrict__ b1,
    const float* __restrict__ a1p, const float* __restrict__ br)
{
  extern __shared__ float sm[];
  float* xs  = sm;           // 32*68 = 2176
  float* x1s = sm + 2176;    // 64*68 = 4352
  float* fs  = x1s + 4352;   // 32*68 = 2176
  const int t  = threadIdx.x;
  const int h  = blockIdx.x;
  const int p0 = blockIdx.y * 64;
  const int b  = blockIdx.z;
  const float a1 = *a1p;

  // conv1: thread = 8oc(4 pairs) x 2px
  const int oc0 = (t >> 5) * 8;
  const int px0 = (t & 31) * 2;
  u64p acc[4][2];
  #pragma unroll
  for (int o2 = 0; o2 < 4; o2++) {
    u64p bp = pk(b1[oc0+2*o2], b1[oc0+2*o2+1]);
    acc[o2][0] = bp; acc[o2][1] = bp;
  }
  const float* xb = x + (b*128)*HWc + h*Wc + p0;
  for (int cc = 0; cc < 4; cc++) {
    __syncthreads();
    for (int i = t; i < 2048; i += 256) {
      int ci = i >> 6, p = i & 63;
      xs[ci*68 + p] = xb[(cc*32 + ci)*HWc + p];
    }
    __syncthreads();
    #pragma unroll 2
    for (int ci = 0; ci < 32; ci++) {
      const int c = cc*32 + ci;
      ulonglong2 wa = *(const ulonglong2*)&g_w1t[c*64 + oc0];
      ulonglong2 wb = *(const ulonglong2*)&g_w1t[c*64 + oc0 + 4];
      float2 xv = *(const float2*)&xs[ci*68 + px0];
      u64p xd0 = pk(xv.x, xv.x), xd1 = pk(xv.y, xv.y);
      u64p wd[4] = {wa.x, wa.y, wb.x, wb.y};
      #pragma unroll
      for (int o2 = 0; o2 < 4; o2++) {
        fma2(acc[o2][0], wd[o2], xd0);
        fma2(acc[o2][1], wd[o2], xd1);
      }
    }
  }
  float* gx1b = g_x1 + (b*64)*HWc + h*Wc + p0;
  #pragma unroll
  for (int o2 = 0; o2 < 4; o2++) {
    float2 v0 = up(acc[o2][0]);   // (oc even, oc odd) @ px0
    float2 v1 = up(acc[o2][1]);   // @ px0+1
    float e0 = (v0.x >= 0.f) ? v0.x : a1*v0.x;
    float e1 = (v1.x >= 0.f) ? v1.x : a1*v1.x;
    float d0 = (v0.y >= 0.f) ? v0.y : a1*v0.y;
    float d1 = (v1.y >= 0.f) ? v1.y : a1*v1.y;
    *(float2*)&x1s[(oc0+2*o2)*68 + px0]   = make_float2(e0, e1);
    *(float2*)&x1s[(oc0+2*o2+1)*68 + px0] = make_float2(d0, d1);
    *(float2*)&gx1b[(oc0+2*o2)*HWc + px0]   = make_float2(e0, e1);
    *(float2*)&gx1b[(oc0+2*o2+1)*HWc + px0] = make_float2(d0, d1);
  }
  __syncthreads();

  // reduce: thread = 8oc(4 pairs) x 1px
  const int ocr = (t >> 6) * 8;
  const int pxr = t & 63;
  u64p racc[4];
  #pragma unroll
  for (int o2 = 0; o2 < 4; o2++) racc[o2] = pk(br[ocr+2*o2], br[ocr+2*o2+1]);
  #pragma unroll 2
  for (int c = 0; c < 64; c++) {
    ulonglong2 wa = *(const ulonglong2*)&g_wrt[c*32 + ocr];
    ulonglong2 wb = *(const ulonglong2*)&g_wrt[c*32 + ocr + 4];
    float xv = x1s[c*68 + pxr];
    u64p xd = pk(xv, xv);
    fma2(racc[0], wa.x, xd);
    fma2(racc[1], wa.y, xd);
    fma2(racc[2], wb.x, xd);
    fma2(racc[3], wb.y, xd);
  }
  float* gfb = g_f + (b*32)*HWc + h*Wc + p0;
  #pragma unroll
  for (int o2 = 0; o2 < 4; o2++) {
    float2 v = up(racc[o2]);
    float e = fmaxf(v.x, 0.f), o = fmaxf(v.y, 0.f);
    fs[(ocr+2*o2)*68 + pxr]   = e;
    fs[(ocr+2*o2+1)*68 + pxr] = o;
    gfb[(ocr+2*o2)*HWc + pxr]   = e;
    gfb[(ocr+2*o2+1)*HWc + pxr] = o;
  }
  __syncthreads();

  if (t < 64) {
    float mx = -1e30f, sum = 0.f;
    #pragma unroll
    for (int c = 0; c < 32; c++) {
      float v = fs[c*68 + t];
      mx = fmaxf(mx, v);
      sum += v;
    }
    g_zp[(b*2)*HWc + h*Wc + p0 + t]   = mx;
    g_zp[(b*2+1)*HWc + h*Wc + p0 + t] = sum * (1.f/32.f);
  }
}

// ---------------------------------------------------------------------------
// K2: involution (unchanged from passing R3 version).
// ---------------------------------------------------------------------------
__global__ __launch_bounds__(256, 2) void k_inv(
    const float* __restrict__ ws, const float* __restrict__ bs,
    const float* __restrict__ a2p)
{
  extern __shared__ float sm[];
  float* x1h = sm;                // 64ch * 8row * 38col = 19456
  float* wss = x1h + 19456;       // 6272
  float* bss = wss + 6272;        // 196
  float* fts = bss + 196;         // 64*33
  const int t = threadIdx.x;
  const int w0 = blockIdx.x << 5;
  const int h0 = blockIdx.y << 1;
  const int b  = blockIdx.z;
  const float a2 = *a2p;

  const float* gx1b = g_x1 + (b*64)*HWc;
  for (int i = t; i < 19456; i += 256) {
    int ch = i / 304, r = i - ch*304;
    int yy = r / 38, xx = r - yy*38;
    int gh = h0 - 3 + yy, gw = w0 - 3 + xx;
    float v = 0.f;
    if ((unsigned)gh < 128u && (unsigned)gw < 128u)
      v = gx1b[ch*HWc + gh*Wc + gw];
    x1h[i] = v;
  }
  for (int i = t; i < 6272; i += 256) wss[i] = ws[i];
  if (t < 196) bss[t] = bs[t];
  const float* gfb = g_f + (b*32)*HWc;
  for (int i = t; i < 2048; i += 256) {
    int c = i >> 6, p = i & 63;
    fts[p*33 + c] = gfb[c*HWc + (h0 + (p>>5))*Wc + w0 + (p&31)];
  }
  __syncthreads();

  const int p = t & 63, j = t >> 6;
  const int py = p >> 5, px = p & 31;

  u64p fp[16];
  #pragma unroll
  for (int c2 = 0; c2 < 16; c2++)
    fp[c2] = pk(fts[p*33 + 2*c2], fts[p*33 + 2*c2 + 1]);

  float acc[16];
  #pragma unroll
  for (int ch = 0; ch < 16; ch++) acc[ch] = 0.f;

  const float* wb = wss + j*49*32;
  const float* bb = bss + j*49;
  const float* xb = x1h + (j*16)*304 + py*38 + px;

  #pragma unroll 1
  for (int dy = 0; dy < 7; dy++) {
    #pragma unroll 1
    for (int dx = 0; dx < 7; dx++) {
      const int tt = dy*7 + dx;
      const float* wr2 = wb + tt*32;
      u64p k0 = 0ull, k1 = 0ull;
      #pragma unroll
      for (int c4 = 0; c4 < 8; c4++) {
        float4 wv = *(const float4*)&wr2[c4*4];
        fma2(k0, pk(wv.x, wv.y), fp[2*c4]);
        fma2(k1, pk(wv.z, wv.w), fp[2*c4 + 1]);
      }
      float2 ka = up(k0), kb = up(k1);
      const float kwt = bb[tt] + ((ka.x + ka.y) + (kb.x + kb.y));
      const float* src = xb + dy*38 + dx;
      #pragma unroll
      for (int ch = 0; ch < 16; ch++)
        acc[ch] += kwt * src[ch*304];
    }
  }

  float* gx2b = g_x2 + (b*64 + j*16)*HWc + (h0 + py)*Wc + (w0 + px);
  #pragma unroll
  for (int ch = 0; ch < 16; ch++) {
    float v = acc[ch];
    gx2b[ch*HWc] = (v >= 0.f) ? v : a2*v;
  }
}

// ---------------------------------------------------------------------------
// K3: psec 3x3 (32->32)+PReLU. Tile 16x4 (grid 512). Weights via broadcast LDG.
// Thread = 8oc(4 pairs) x 1px.
// ---------------------------------------------------------------------------
__global__ __launch_bounds__(256, 4) void k_psec1(
    const float* __restrict__ bp1, const float* __restrict__ app)
{
  extern __shared__ float sm[];
  float* fh = sm;   // 32ch * 6row * 18col = 3456
  const int t = threadIdx.x;
  const int w0 = blockIdx.x << 4;   // 8 x-tiles of 16
  const int h0 = blockIdx.y << 2;   // 32 y-tiles of 4
  const int b  = blockIdx.z;
  const float ap = *app;

  const float* gfb = g_f + (b*32)*HWc;
  for (int i = t; i < 3456; i += 256) {
    int c = i / 108, r = i - c*108;
    int yy = r / 18, xx = r - yy*18;
    int gh = h0 - 1 + yy, gw = w0 - 1 + xx;
    float v = 0.f;
    if ((unsigned)gh < 128u && (unsigned)gw < 128u)
      v = gfb[c*HWc + gh*Wc + gw];
    fh[i] = v;
  }
  __syncthreads();

  const int oc0 = (t >> 6) * 8;
  const int pg  = t & 63;
  const int py  = pg >> 4;           // 0..3
  const int px  = pg & 15;           // 0..15

  u64p acc[4];
  #pragma unroll
  for (int o2 = 0; o2 < 4; o2++) acc[o2] = pk(bp1[oc0+2*o2], bp1[oc0+2*o2+1]);

  #pragma unroll 1
  for (int ci = 0; ci < 32; ci++) {
    #pragma unroll
    for (int tap = 0; tap < 9; tap++) {
      const int di = tap / 3, dj = tap - di*3;
      ulonglong2 wa = *(const ulonglong2*)&g_wp1t[(ci*9 + tap)*32 + oc0];
      ulonglong2 wb = *(const ulonglong2*)&g_wp1t[(ci*9 + tap)*32 + oc0 + 4];
      float fv = fh[ci*108 + (py + di)*18 + (px + dj)];
      u64p xd = pk(fv, fv);
      fma2(acc[0], wa.x, xd);
      fma2(acc[1], wa.y, xd);
      fma2(acc[2], wb.x, xd);
      fma2(acc[3], wb.y, xd);
    }
  }

  float* ghb = g_h + (b*32)*HWc + (h0 + py)*Wc + (w0 + px);
  #pragma unroll
  for (int o2 = 0; o2 < 4; o2++) {
    float2 v = up(acc[o2]);
    float e = (v.x >= 0.f) ? v.x : ap*v.x;
    float o = (v.y >= 0.f) ? v.y : ap*v.y;
    ghb[(oc0+2*o2)*HWc]   = e;
    ghb[(oc0+2*o2+1)*HWc] = o;
  }
}

// ---------------------------------------------------------------------------
// K4: half-row (64 px), 128 oc. Thread = 8oc(4 pairs) x 4px.
// conv2 + attention gate + psec 1x1, weights via LDG (L1).
// ---------------------------------------------------------------------------
__global__ __launch_bounds__(256, 3) void k_final(
    const float* __restrict__ b2,  const float* __restrict__ wa,
    const float* __restrict__ ba,  const float* __restrict__ bp2,
    float* __restrict__ out)
{
  extern __shared__ float sm[];
  float* x2t   = sm;              // 64*68 = 4352
  float* ht    = x2t + 4352;      // 32*68 = 2176
  float* zph   = ht + 2176;       // 2*7*70 = 980
  float* was   = zph + 980;       // 98
  float* attns = was + 98;        // 64   -> total 7670
  const int t  = threadIdx.x;
  const int h  = blockIdx.x;
  const int p0 = blockIdx.y * 64;
  const int b  = blockIdx.z;

  const float* gx2b = g_x2 + (b*64)*HWc + h*Wc + p0;
  for (int i = t; i < 4096; i += 256) { int c = i >> 6, p = i & 63; x2t[c*68 + p] = gx2b[c*HWc + p]; }
  const float* ghb = g_h + (b*32)*HWc + h*Wc + p0;
  for (int i = t; i < 2048; i += 256) { int c = i >> 6, p = i & 63; ht[c*68 + p] = ghb[c*HWc + p]; }
  const float* gzb = g_zp + (b*2)*HWc;
  for (int i = t; i < 980; i += 256) {
    int c = i / 490, r = i - c*490;
    int yy = r / 70, xx = r - yy*70;
    int gh = h - 3 + yy, gw = p0 - 3 + xx;
    float v = 0.f;
    if ((unsigned)gh < 128u && (unsigned)gw < 128u)
      v = gzb[c*HWc + gh*Wc + gw];
    zph[i] = v;
  }
  if (t < 98) was[t] = wa[t];
  __syncthreads();

  if (t < 64) {
    float aacc = *ba;
    #pragma unroll
    for (int dy = 0; dy < 7; dy++)
      #pragma unroll
      for (int dx = 0; dx < 7; dx++) {
        const int o1 = dy*70 + t + dx;
        aacc += was[dy*7+dx]*zph[o1] + was[49 + dy*7+dx]*zph[490 + o1];
      }
    attns[t] = 1.f / (1.f + expf(-aacc));
  }
  __syncthreads();

  const int oc0 = (t >> 4) * 8;     // 16 groups x 8 oc = 128
  const int px0 = (t & 15) * 4;     // 16 groups x 4 px = 64
  u64p acc[4][4];
  #pragma unroll
  for (int o2 = 0; o2 < 4; o2++) {
    u64p bp = pk(b2[oc0+2*o2], b2[oc0+2*o2+1]);
    #pragma unroll
    for (int p = 0; p < 4; p++) acc[o2][p] = bp;
  }

  #pragma unroll 2
  for (int c = 0; c < 64; c++) {
    ulonglong2 wa2 = *(const ulonglong2*)&g_w2t[c*128 + oc0];
    ulonglong2 wb2 = *(const ulonglong2*)&g_w2t[c*128 + oc0 + 4];
    float4 xv = *(const float4*)&x2t[c*68 + px0];
    u64p xd[4] = {pk(xv.x,xv.x), pk(xv.y,xv.y), pk(xv.z,xv.z), pk(xv.w,xv.w)};
    u64p wd[4] = {wa2.x, wa2.y, wb2.x, wb2.y};
    #pragma unroll
    for (int o2 = 0; o2 < 4; o2++)
      #pragma unroll
      for (int p = 0; p < 4; p++)
        fma2(acc[o2][p], wd[o2], xd[p]);
  }

  u64p attp[4];
  #pragma unroll
  for (int p = 0; p < 4; p++) { float a = attns[px0 + p]; attp[p] = pk(a, a); }
  #pragma unroll
  for (int o2 = 0; o2 < 4; o2++) {
    u64p bpp = pk(bp2[oc0+2*o2], bp2[oc0+2*o2+1]);
    #pragma unroll
    for (int p = 0; p < 4; p++) fma2b(acc[o2][p], attp[p], bpp);
  }

  #pragma unroll 2
  for (int c = 0; c < 32; c++) {
    ulonglong2 wa2 = *(const ulonglong2*)&g_wp2t[c*128 + oc0];
    ulonglong2 wb2 = *(const ulonglong2*)&g_wp2t[c*128 + oc0 + 4];
    float4 hv = *(const float4*)&ht[c*68 + px0];
    u64p hd[4] = {pk(hv.x,hv.x), pk(hv.y,hv.y), pk(hv.z,hv.z), pk(hv.w,hv.w)};
    u64p wd[4] = {wa2.x, wa2.y, wb2.x, wb2.y};
    #pragma unroll
    for (int o2 = 0; o2 < 4; o2++)
      #pragma unroll
      for (int p = 0; p < 4; p++)
        fma2(acc[o2][p], wd[o2], hd[p]);
  }

  float* ob = out + (b*128)*HWc + h*Wc + p0 + px0;
  #pragma unroll
  for (int o2 = 0; o2 < 4; o2++) {
    float2 q0 = up(acc[o2][0]), q1 = up(acc[o2][1]), q2 = up(acc[o2][2]), q3 = up(acc[o2][3]);
    *(float4*)&ob[(oc0+2*o2)*HWc]   = make_float4(q0.x, q1.x, q2.x, q3.x);
    *(float4*)&ob[(oc0+2*o2+1)*HWc] = make_float4(q0.y, q1.y, q2.y, q3.y);
  }
}

// ---------------------------------------------------------------------------
extern "C" void kernel_launch(void* const* d_in, const int* in_sizes, int n_in,
                              void* d_out, int out_size)
{
  const float* x   = (const float*)d_in[0];
  const float* w1  = (const float*)d_in[1];
  const float* b1  = (const float*)d_in[2];
  const float* a1  = (const float*)d_in[3];
  const float* wr  = (const float*)d_in[4];
  const float* br  = (const float*)d_in[5];
  const float* ws  = (const float*)d_in[6];
  const float* bs  = (const float*)d_in[7];
  const float* a2  = (const float*)d_in[8];
  const float* w2  = (const float*)d_in[9];
  const float* b2  = (const float*)d_in[10];
  const float* wa  = (const float*)d_in[11];
  const float* ba  = (const float*)d_in[12];
  const float* wp1 = (const float*)d_in[13];
  const float* bp1 = (const float*)d_in[14];
  const float* ap  = (const float*)d_in[15];
  const float* wp2 = (const float*)d_in[16];
  const float* bp2 = (const float*)d_in[17];
  float* out = (float*)d_out;

  const int s1 = 8704  * 4;   // k_front
  const int s2 = 28036 * 4;   // k_inv
  const int s3 = 3456  * 4;   // k_psec1
  const int s4 = 7670  * 4;   // k_final

  cudaFuncSetAttribute(k_front, cudaFuncAttributeMaxDynamicSharedMemorySize, s1);
  cudaFuncSetAttribute(k_inv,   cudaFuncAttributeMaxDynamicSharedMemorySize, s2);
  cudaFuncSetAttribute(k_psec1, cudaFuncAttributeMaxDynamicSharedMemorySize, s3);
  cudaFuncSetAttribute(k_final, cudaFuncAttributeMaxDynamicSharedMemorySize, s4);

  k_prep <<<32, 256>>>(w1, wr, w2, wp2, wp1);
  k_front<<<dim3(128, 2, 2), 256, s1>>>(x, b1, a1, br);
  k_inv  <<<dim3(4, 64, 2),  256, s2>>>(ws, bs, a2);
  k_psec1<<<dim3(8, 32, 2),  256, s3>>>(bp1, ap);
  k_final<<<dim3(128, 2, 2), 256, s4>>>(b2, wa, ba, bp2, out);
}

// round 8
// speedup vs baseline: 1.0767x; 1.0767x over previous
#include <cuda_runtime.h>
#include <math.h>

#define Hc 128
#define Wc 128
#define HWc 16384

typedef unsigned long long u64p;

__device__ __forceinline__ u64p pk(float lo, float hi) {
  u64p r; asm("mov.b64 %0, {%1,%2};" : "=l"(r) : "f"(lo), "f"(hi)); return r;
}
__device__ __forceinline__ void fma2(u64p& a, u64p x, u64p y) {
  asm("fma.rn.f32x2 %0, %1, %2, %0;" : "+l"(a) : "l"(x), "l"(y));
}
__device__ __forceinline__ void fma2b(u64p& a, u64p x, u64p c) {
  asm("fma.rn.f32x2 %0, %0, %1, %2;" : "+l"(a) : "l"(x), "l"(c));
}
__device__ __forceinline__ float2 up(u64p v) {
  float2 f; asm("mov.b64 {%0,%1}, %2;" : "=f"(f.x), "=f"(f.y) : "l"(v)); return f;
}

// activations scratch
__device__ float g_x1[2*64*HWc];
__device__ float g_f [2*32*HWc];
__device__ float g_zp[2*2*HWc];
__device__ float g_x2[2*64*HWc];
__device__ float g_h [2*32*HWc];

// ---------------------------------------------------------------------------
// K1: half-row (64 px). conv1 (128->64)+PReLU -> x1; reduce (64->32)+ReLU -> f;
// ZPool -> zp. Weights in smem; thread tile 4oc x 4px; 3 CTAs/SM.
// ---------------------------------------------------------------------------
__global__ __launch_bounds__(256, 3) void k_front(
    const float* __restrict__ x,  const float* __restrict__ w1,
    const float* __restrict__ b1, const float* __restrict__ a1p,
    const float* __restrict__ wr, const float* __restrict__ br)
{
  extern __shared__ float sm[];
  float* xs  = sm;             // 32*68 = 2176
  float* w1t = xs + 2176;      // 8192 [c][oc]
  float* x1s = w1t + 8192;     // 64*68 = 4352
  float* wrt = x1s + 4352;     // 2048 [c][oc]
  float* fs  = wrt + 2048;     // 32*68 = 2176   total 18944 fl = 75776 B
  const int t  = threadIdx.x;
  const int h  = blockIdx.x;
  const int p0 = blockIdx.y * 64;
  const int b  = blockIdx.z;
  const float a1 = *a1p;

  for (int i = t; i < 8192; i += 256) { int c = i >> 6, oc = i & 63; w1t[i] = w1[oc*128 + c]; }
  for (int i = t; i < 2048; i += 256) { int c = i >> 5, oc = i & 31; wrt[i] = wr[oc*64 + c]; }

  // conv1: thread = 4oc(2 pairs) x 4px
  const int oc0 = (t >> 4) * 4;       // 16 groups x 4 = 64 oc
  const int px0 = (t & 15) * 4;       // 16 groups x 4 = 64 px
  u64p acc[2][4];
  {
    u64p bp0 = pk(b1[oc0], b1[oc0+1]);
    u64p bp1v = pk(b1[oc0+2], b1[oc0+3]);
    #pragma unroll
    for (int p = 0; p < 4; p++) { acc[0][p] = bp0; acc[1][p] = bp1v; }
  }

  const float* xb = x + (b*128)*HWc + h*Wc + p0;
  for (int cc = 0; cc < 4; cc++) {
    __syncthreads();
    for (int i = t; i < 2048; i += 256) {
      int ci = i >> 6, p = i & 63;
      xs[ci*68 + p] = xb[(cc*32 + ci)*HWc + p];
    }
    __syncthreads();
    #pragma unroll 4
    for (int ci = 0; ci < 32; ci++) {
      const int c = cc*32 + ci;
      ulonglong2 wv = *(const ulonglong2*)&w1t[c*64 + oc0];
      float4 xv = *(const float4*)&xs[ci*68 + px0];
      u64p xd[4] = {pk(xv.x,xv.x), pk(xv.y,xv.y), pk(xv.z,xv.z), pk(xv.w,xv.w)};
      #pragma unroll
      for (int p = 0; p < 4; p++) {
        fma2(acc[0][p], wv.x, xd[p]);
        fma2(acc[1][p], wv.y, xd[p]);
      }
    }
  }

  float* gx1b = g_x1 + (b*64)*HWc + h*Wc + p0;
  #pragma unroll
  for (int o2 = 0; o2 < 2; o2++) {
    float2 v0 = up(acc[o2][0]), v1 = up(acc[o2][1]), v2 = up(acc[o2][2]), v3 = up(acc[o2][3]);
    float4 ev = make_float4((v0.x>=0.f)?v0.x:a1*v0.x, (v1.x>=0.f)?v1.x:a1*v1.x,
                            (v2.x>=0.f)?v2.x:a1*v2.x, (v3.x>=0.f)?v3.x:a1*v3.x);
    float4 od = make_float4((v0.y>=0.f)?v0.y:a1*v0.y, (v1.y>=0.f)?v1.y:a1*v1.y,
                            (v2.y>=0.f)?v2.y:a1*v2.y, (v3.y>=0.f)?v3.y:a1*v3.y);
    *(float4*)&x1s[(oc0+2*o2)*68 + px0]   = ev;
    *(float4*)&x1s[(oc0+2*o2+1)*68 + px0] = od;
    *(float4*)&gx1b[(oc0+2*o2)*HWc + px0]   = ev;
    *(float4*)&gx1b[(oc0+2*o2+1)*HWc + px0] = od;
  }
  __syncthreads();

  // reduce: thread = 2oc(1 pair) x 4px
  const int ocr = (t >> 4) * 2;       // 16 groups x 2 = 32 oc
  const int pxr = (t & 15) * 4;
  u64p racc[4];
  {
    u64p bp = pk(br[ocr], br[ocr+1]);
    #pragma unroll
    for (int p = 0; p < 4; p++) racc[p] = bp;
  }
  #pragma unroll 4
  for (int c = 0; c < 64; c++) {
    u64p wv = *(const u64p*)&wrt[c*32 + ocr];
    float4 xv = *(const float4*)&x1s[c*68 + pxr];
    fma2(racc[0], wv, pk(xv.x,xv.x));
    fma2(racc[1], wv, pk(xv.y,xv.y));
    fma2(racc[2], wv, pk(xv.z,xv.z));
    fma2(racc[3], wv, pk(xv.w,xv.w));
  }
  float* gfb = g_f + (b*32)*HWc + h*Wc + p0;
  {
    float2 v0 = up(racc[0]), v1 = up(racc[1]), v2 = up(racc[2]), v3 = up(racc[3]);
    float4 ev = make_float4(fmaxf(v0.x,0.f), fmaxf(v1.x,0.f), fmaxf(v2.x,0.f), fmaxf(v3.x,0.f));
    float4 od = make_float4(fmaxf(v0.y,0.f), fmaxf(v1.y,0.f), fmaxf(v2.y,0.f), fmaxf(v3.y,0.f));
    *(float4*)&fs[ocr*68 + pxr]     = ev;
    *(float4*)&fs[(ocr+1)*68 + pxr] = od;
    *(float4*)&gfb[ocr*HWc + pxr]     = ev;
    *(float4*)&gfb[(ocr+1)*HWc + pxr] = od;
  }
  __syncthreads();

  if (t < 64) {
    float mx = -1e30f, sum = 0.f;
    #pragma unroll
    for (int c = 0; c < 32; c++) {
      float v = fs[c*68 + t];
      mx = fmaxf(mx, v);
      sum += v;
    }
    g_zp[(b*2)*HWc + h*Wc + p0 + t]   = mx;
    g_zp[(b*2+1)*HWc + h*Wc + p0 + t] = sum * (1.f/32.f);
  }
}

// ---------------------------------------------------------------------------
// K2: involution (R3 version, smem weights). Tile 32x2 px.
// ---------------------------------------------------------------------------
__global__ __launch_bounds__(256, 2) void k_inv(
    const float* __restrict__ ws, const float* __restrict__ bs,
    const float* __restrict__ a2p)
{
  extern __shared__ float sm[];
  float* x1h = sm;                // 64ch * 8row * 38col = 19456
  float* wss = x1h + 19456;       // 6272
  float* bss = wss + 6272;        // 196
  float* fts = bss + 196;         // 64*33
  const int t = threadIdx.x;
  const int w0 = blockIdx.x << 5;
  const int h0 = blockIdx.y << 1;
  const int b  = blockIdx.z;
  const float a2 = *a2p;

  const float* gx1b = g_x1 + (b*64)*HWc;
  for (int i = t; i < 19456; i += 256) {
    int ch = i / 304, r = i - ch*304;
    int yy = r / 38, xx = r - yy*38;
    int gh = h0 - 3 + yy, gw = w0 - 3 + xx;
    float v = 0.f;
    if ((unsigned)gh < 128u && (unsigned)gw < 128u)
      v = gx1b[ch*HWc + gh*Wc + gw];
    x1h[i] = v;
  }
  for (int i = t; i < 6272; i += 256) wss[i] = ws[i];
  if (t < 196) bss[t] = bs[t];
  const float* gfb = g_f + (b*32)*HWc;
  for (int i = t; i < 2048; i += 256) {
    int c = i >> 6, p = i & 63;
    fts[p*33 + c] = gfb[c*HWc + (h0 + (p>>5))*Wc + w0 + (p&31)];
  }
  __syncthreads();

  const int p = t & 63, j = t >> 6;
  const int py = p >> 5, px = p & 31;

  u64p fp[16];
  #pragma unroll
  for (int c2 = 0; c2 < 16; c2++)
    fp[c2] = pk(fts[p*33 + 2*c2], fts[p*33 + 2*c2 + 1]);

  float acc[16];
  #pragma unroll
  for (int ch = 0; ch < 16; ch++) acc[ch] = 0.f;

  const float* wb = wss + j*49*32;
  const float* bb = bss + j*49;
  const float* xb = x1h + (j*16)*304 + py*38 + px;

  #pragma unroll 1
  for (int dy = 0; dy < 7; dy++) {
    #pragma unroll 1
    for (int dx = 0; dx < 7; dx++) {
      const int tt = dy*7 + dx;
      const float* wr2 = wb + tt*32;
      u64p k0 = 0ull, k1 = 0ull;
      #pragma unroll
      for (int c4 = 0; c4 < 8; c4++) {
        float4 wv = *(const float4*)&wr2[c4*4];
        fma2(k0, pk(wv.x, wv.y), fp[2*c4]);
        fma2(k1, pk(wv.z, wv.w), fp[2*c4 + 1]);
      }
      float2 ka = up(k0), kb = up(k1);
      const float kwt = bb[tt] + ((ka.x + ka.y) + (kb.x + kb.y));
      const float* src = xb + dy*38 + dx;
      #pragma unroll
      for (int ch = 0; ch < 16; ch++)
        acc[ch] += kwt * src[ch*304];
    }
  }

  float* gx2b = g_x2 + (b*64 + j*16)*HWc + (h0 + py)*Wc + (w0 + px);
  #pragma unroll
  for (int ch = 0; ch < 16; ch++) {
    float v = acc[ch];
    gx2b[ch*HWc] = (v >= 0.f) ? v : a2*v;
  }
}

// ---------------------------------------------------------------------------
// K3: psec 3x3 (32->32)+PReLU. R3 version: tile 16x8, smem weights.
// ---------------------------------------------------------------------------
__global__ __launch_bounds__(256) void k_psec1(
    const float* __restrict__ wp1, const float* __restrict__ bp1,
    const float* __restrict__ app)
{
  extern __shared__ float sm[];
  float* fh  = sm;            // 32*180 = 5760
  float* wpt = fh + 5760;     // 9216 [ci*9+tap][oc]
  const int t = threadIdx.x;
  const int w0 = blockIdx.x << 4;
  const int h0 = blockIdx.y << 3;
  const int b  = blockIdx.z;
  const float ap = *app;

  const float* gfb = g_f + (b*32)*HWc;
  for (int i = t; i < 5760; i += 256) {
    int c = i / 180, r = i - c*180;
    int yy = r / 18, xx = r - yy*18;
    int gh = h0 - 1 + yy, gw = w0 - 1 + xx;
    float v = 0.f;
    if ((unsigned)gh < 128u && (unsigned)gw < 128u)
      v = gfb[c*HWc + gh*Wc + gw];
    fh[i] = v;
  }
  for (int i = t; i < 9216; i += 256) {
    int tc = i >> 5, o = i & 31;
    wpt[i] = wp1[o*288 + tc];
  }
  __syncthreads();

  const int oc0 = (t >> 6) * 8;          // 4 groups x 8 oc
  const int pg  = t & 63;
  const int py  = pg >> 3;               // 0..7
  const int px0 = (pg & 7) * 2;          // 0..14

  u64p acc[4][2];
  #pragma unroll
  for (int o2 = 0; o2 < 4; o2++) {
    u64p bp = pk(bp1[oc0 + 2*o2], bp1[oc0 + 2*o2 + 1]);
    acc[o2][0] = bp; acc[o2][1] = bp;
  }

  #pragma unroll 1
  for (int ci = 0; ci < 32; ci++) {
    #pragma unroll
    for (int tap = 0; tap < 9; tap++) {
      const int di = tap / 3, dj = tap - di*3;
      ulonglong2 wa = *(const ulonglong2*)&wpt[(ci*9 + tap)*32 + oc0];
      ulonglong2 wb = *(const ulonglong2*)&wpt[(ci*9 + tap)*32 + oc0 + 4];
      const float* fr = &fh[ci*180 + (py + di)*18 + px0 + dj];
      u64p xd0 = pk(fr[0], fr[0]), xd1 = pk(fr[1], fr[1]);
      fma2(acc[0][0], wa.x, xd0); fma2(acc[0][1], wa.x, xd1);
      fma2(acc[1][0], wa.y, xd0); fma2(acc[1][1], wa.y, xd1);
      fma2(acc[2][0], wb.x, xd0); fma2(acc[2][1], wb.x, xd1);
      fma2(acc[3][0], wb.y, xd0); fma2(acc[3][1], wb.y, xd1);
    }
  }

  float* ghb = g_h + (b*32)*HWc + (h0 + py)*Wc + (w0 + px0);
  #pragma unroll
  for (int o2 = 0; o2 < 4; o2++) {
    float2 v0 = up(acc[o2][0]);
    float2 v1 = up(acc[o2][1]);
    float a0 = (v0.x >= 0.f) ? v0.x : ap*v0.x;
    float b0 = (v0.y >= 0.f) ? v0.y : ap*v0.y;
    float a1v = (v1.x >= 0.f) ? v1.x : ap*v1.x;
    float b1v = (v1.y >= 0.f) ? v1.y : ap*v1.y;
    *(float2*)&ghb[(oc0 + 2*o2)*HWc]     = make_float2(a0, a1v);
    *(float2*)&ghb[(oc0 + 2*o2 + 1)*HWc] = make_float2(b0, b1v);
  }
}

// ---------------------------------------------------------------------------
// K4: oc-split (64 oc per CTA) x half-row (64 px). Thread = 4oc x 4px.
// smem ~55KB, 4 CTAs/SM. conv2 + attn gate + psec 1x1.
// ---------------------------------------------------------------------------
__global__ __launch_bounds__(256, 4) void k_final(
    const float* __restrict__ w2,  const float* __restrict__ b2,
    const float* __restrict__ wa,  const float* __restrict__ ba,
    const float* __restrict__ wp2, const float* __restrict__ bp2,
    float* __restrict__ out)
{
  extern __shared__ float sm[];
  float* x2t   = sm;              // 64*68 = 4352
  float* ht    = x2t + 4352;      // 32*68 = 2176
  float* w2t   = ht + 2176;       // 64*64 = 4096 [c][oc-local]
  float* wpt   = w2t + 4096;      // 32*64 = 2048
  float* zph   = wpt + 2048;      // 2*7*70 = 980
  float* was   = zph + 980;       // 98
  float* attns = was + 98;        // 64    total 13814 fl = 55256 B
  const int t  = threadIdx.x;
  const int h  = blockIdx.x;
  const int p0 = (blockIdx.y & 1) * 64;
  const int ocb = (blockIdx.y >> 1) * 64;
  const int b  = blockIdx.z;

  const float* gx2b = g_x2 + (b*64)*HWc + h*Wc + p0;
  for (int i = t; i < 4096; i += 256) { int c = i >> 6, p = i & 63; x2t[c*68 + p] = gx2b[c*HWc + p]; }
  const float* ghb = g_h + (b*32)*HWc + h*Wc + p0;
  for (int i = t; i < 2048; i += 256) { int c = i >> 6, p = i & 63; ht[c*68 + p] = ghb[c*HWc + p]; }
  for (int i = t; i < 4096; i += 256) { int c = i >> 6, o = i & 63; w2t[i] = w2[(ocb + o)*64 + c]; }
  for (int i = t; i < 2048; i += 256) { int c = i >> 6, o = i & 63; wpt[i] = wp2[(ocb + o)*32 + c]; }
  const float* gzb = g_zp + (b*2)*HWc;
  for (int i = t; i < 980; i += 256) {
    int c = i / 490, r = i - c*490;
    int yy = r / 70, xx = r - yy*70;
    int gh = h - 3 + yy, gw = p0 - 3 + xx;
    float v = 0.f;
    if ((unsigned)gh < 128u && (unsigned)gw < 128u)
      v = gzb[c*HWc + gh*Wc + gw];
    zph[i] = v;
  }
  if (t < 98) was[t] = wa[t];
  __syncthreads();

  if (t < 64) {
    float aacc = *ba;
    #pragma unroll
    for (int dy = 0; dy < 7; dy++)
      #pragma unroll
      for (int dx = 0; dx < 7; dx++) {
        const int o1 = dy*70 + t + dx;
        aacc += was[dy*7+dx]*zph[o1] + was[49 + dy*7+dx]*zph[490 + o1];
      }
    attns[t] = 1.f / (1.f + expf(-aacc));
  }
  __syncthreads();

  const int oc0 = (t >> 4) * 4;     // local oc in [0,64)
  const int px0 = (t & 15) * 4;
  u64p acc[2][4];
  {
    u64p bp0 = pk(b2[ocb+oc0], b2[ocb+oc0+1]);
    u64p bp1v = pk(b2[ocb+oc0+2], b2[ocb+oc0+3]);
    #pragma unroll
    for (int p = 0; p < 4; p++) { acc[0][p] = bp0; acc[1][p] = bp1v; }
  }

  #pragma unroll 4
  for (int c = 0; c < 64; c++) {
    ulonglong2 wv = *(const ulonglong2*)&w2t[c*64 + oc0];
    float4 xv = *(const float4*)&x2t[c*68 + px0];
    u64p xd[4] = {pk(xv.x,xv.x), pk(xv.y,xv.y), pk(xv.z,xv.z), pk(xv.w,xv.w)};
    #pragma unroll
    for (int p = 0; p < 4; p++) {
      fma2(acc[0][p], wv.x, xd[p]);
      fma2(acc[1][p], wv.y, xd[p]);
    }
  }

  {
    u64p bpp0 = pk(bp2[ocb+oc0], bp2[ocb+oc0+1]);
    u64p bpp1 = pk(bp2[ocb+oc0+2], bp2[ocb+oc0+3]);
    #pragma unroll
    for (int p = 0; p < 4; p++) {
      float a = attns[px0 + p];
      u64p ap2 = pk(a, a);
      fma2b(acc[0][p], ap2, bpp0);
      fma2b(acc[1][p], ap2, bpp1);
    }
  }

  #pragma unroll 4
  for (int c = 0; c < 32; c++) {
    ulonglong2 wv = *(const ulonglong2*)&wpt[c*64 + oc0];
    float4 hv = *(const float4*)&ht[c*68 + px0];
    u64p hd[4] = {pk(hv.x,hv.x), pk(hv.y,hv.y), pk(hv.z,hv.z), pk(hv.w,hv.w)};
    #pragma unroll
    for (int p = 0; p < 4; p++) {
      fma2(acc[0][p], wv.x, hd[p]);
      fma2(acc[1][p], wv.y, hd[p]);
    }
  }

  float* ob = out + (b*128 + ocb)*HWc + h*Wc + p0;
  #pragma unroll
  for (int o2 = 0; o2 < 2; o2++) {
    float2 v0 = up(acc[o2][0]), v1 = up(acc[o2][1]), v2 = up(acc[o2][2]), v3 = up(acc[o2][3]);
    *(float4*)&ob[(oc0+2*o2)*HWc + px0]   = make_float4(v0.x, v1.x, v2.x, v3.x);
    *(float4*)&ob[(oc0+2*o2+1)*HWc + px0] = make_float4(v0.y, v1.y, v2.y, v3.y);
  }
}

// ---------------------------------------------------------------------------
extern "C" void kernel_launch(void* const* d_in, const int* in_sizes, int n_in,
                              void* d_out, int out_size)
{
  const float* x   = (const float*)d_in[0];
  const float* w1  = (const float*)d_in[1];
  const float* b1  = (const float*)d_in[2];
  const float* a1  = (const float*)d_in[3];
  const float* wr  = (const float*)d_in[4];
  const float* br  = (const float*)d_in[5];
  const float* ws  = (const float*)d_in[6];
  const float* bs  = (const float*)d_in[7];
  const float* a2  = (const float*)d_in[8];
  const float* w2  = (const float*)d_in[9];
  const float* b2  = (const float*)d_in[10];
  const float* wa  = (const float*)d_in[11];
  const float* ba  = (const float*)d_in[12];
  const float* wp1 = (const float*)d_in[13];
  const float* bp1 = (const float*)d_in[14];
  const float* ap  = (const float*)d_in[15];
  const float* wp2 = (const float*)d_in[16];
  const float* bp2 = (const float*)d_in[17];
  float* out = (float*)d_out;

  const int s1 = 18944 * 4;   // k_front  ~75.8 KB -> 3 CTAs
  const int s2 = 28036 * 4;   // k_inv    ~112 KB -> 2 CTAs
  const int s3 = 14976 * 4;   // k_psec1  ~60 KB  -> 3 CTAs
  const int s4 = 13814 * 4;   // k_final  ~55 KB  -> 4 CTAs

  cudaFuncSetAttribute(k_front, cudaFuncAttributeMaxDynamicSharedMemorySize, s1);
  cudaFuncSetAttribute(k_inv,   cudaFuncAttributeMaxDynamicSharedMemorySize, s2);
  cudaFuncSetAttribute(k_psec1, cudaFuncAttributeMaxDynamicSharedMemorySize, s3);
  cudaFuncSetAttribute(k_final, cudaFuncAttributeMaxDynamicSharedMemorySize, s4);

  k_front<<<dim3(128, 2, 2), 256, s1>>>(x, w1, b1, a1, wr, br);
  k_inv  <<<dim3(4, 64, 2),  256, s2>>>(ws, bs, a2);
  k_psec1<<<dim3(8, 16, 2),  256, s3>>>(wp1, bp1, ap);
  k_final<<<dim3(128, 4, 2), 256, s4>>>(w2, b2, wa, ba, wp2, bp2, out);
}

// round 10
// speedup vs baseline: 1.2215x; 1.1345x over previous
#include <cuda_runtime.h>
#include <cuda_bf16.h>
#include <math.h>
#include <cstdint>

#define Hc 128
#define Wc 128
#define HWc 16384

typedef unsigned long long u64p;

__device__ __forceinline__ u64p pk(float lo, float hi) {
  u64p r; asm("mov.b64 %0, {%1,%2};" : "=l"(r) : "f"(lo), "f"(hi)); return r;
}
__device__ __forceinline__ void fma2(u64p& a, u64p x, u64p y) {
  asm("fma.rn.f32x2 %0, %1, %2, %0;" : "+l"(a) : "l"(x), "l"(y));
}
__device__ __forceinline__ float2 up(u64p v) {
  float2 f; asm("mov.b64 {%0,%1}, %2;" : "=f"(f.x), "=f"(f.y) : "l"(v)); return f;
}
__device__ __forceinline__ uint32_t smem_u32(const void* p) {
  uint32_t a;
  asm("{ .reg .u64 t; cvta.to.shared.u64 t, %1; cvt.u32.u64 %0, t; }" : "=r"(a) : "l"(p));
  return a;
}

// activations scratch
__device__ float g_x1[2*64*HWc];
__device__ float g_f [2*32*HWc];
__device__ float g_zp[2*2*HWc];
__device__ float g_x2[2*64*HWc];
__device__ float g_h [2*32*HWc];

// ---------------------------------------------------------------------------
// K1: one row (128 px). conv1 (128->64)+PReLU -> x1 ; reduce (64->32)+ReLU -> f;
// ZPool -> zp. (R3 known-good version.)
// ---------------------------------------------------------------------------
__global__ __launch_bounds__(256, 2) void k_front(
    const float* __restrict__ x,  const float* __restrict__ w1,
    const float* __restrict__ b1, const float* __restrict__ a1p,
    const float* __restrict__ wr, const float* __restrict__ br)
{
  extern __shared__ float sm[];
  float* xs  = sm;              // 32*132
  float* w1t = xs + 4224;       // 8192  [c][oc]
  float* x1s = w1t + 8192;      // 64*132
  float* wrt = x1s + 8448;      // 2048  [c][oc]
  float* fs  = wrt + 2048;      // 32*132
  const int t = threadIdx.x;
  const int h = blockIdx.x & 127;
  const int b = blockIdx.x >> 7;
  const float a1 = *a1p;

  for (int i = t; i < 8192; i += 256) { int c = i >> 6, oc = i & 63; w1t[i] = w1[oc*128 + c]; }
  for (int i = t; i < 2048; i += 256) { int c = i >> 5, oc = i & 31; wrt[i] = wr[oc*64 + c]; }

  const int oc0 = (t >> 4) * 4;
  const int px0 = (t & 15) * 8;
  u64p acc[4][4];
  #pragma unroll
  for (int o = 0; o < 4; o++) {
    float bv = b1[oc0 + o];
    u64p bp = pk(bv, bv);
    #pragma unroll
    for (int p = 0; p < 4; p++) acc[o][p] = bp;
  }

  const float* xb = x + (b*128)*HWc + h*Wc;
  for (int cc = 0; cc < 4; cc++) {
    __syncthreads();
    for (int i = t; i < 4096; i += 256) {
      int ci = i >> 7, p = i & 127;
      xs[ci*132 + p] = xb[(cc*32 + ci)*HWc + p];
    }
    __syncthreads();
    #pragma unroll 4
    for (int ci = 0; ci < 32; ci++) {
      const int c = cc*32 + ci;
      float4 wv  = *(const float4*)&w1t[c*64 + oc0];
      float4 xa  = *(const float4*)&xs[ci*132 + px0];
      float4 xb4 = *(const float4*)&xs[ci*132 + px0 + 4];
      u64p xp[4] = {pk(xa.x,xa.y), pk(xa.z,xa.w), pk(xb4.x,xb4.y), pk(xb4.z,xb4.w)};
      u64p wd[4] = {pk(wv.x,wv.x), pk(wv.y,wv.y), pk(wv.z,wv.z), pk(wv.w,wv.w)};
      #pragma unroll
      for (int o = 0; o < 4; o++)
        #pragma unroll
        for (int p = 0; p < 4; p++)
          fma2(acc[o][p], wd[o], xp[p]);
    }
  }

  float* gx1b = g_x1 + (b*64)*HWc + h*Wc;
  #pragma unroll
  for (int o = 0; o < 4; o++) {
    float v4[8];
    #pragma unroll
    for (int p = 0; p < 4; p++) {
      float2 v = up(acc[o][p]);
      v4[2*p]   = (v.x >= 0.f) ? v.x : a1*v.x;
      v4[2*p+1] = (v.y >= 0.f) ? v.y : a1*v.y;
    }
    *(float4*)&x1s[(oc0+o)*132 + px0]     = make_float4(v4[0],v4[1],v4[2],v4[3]);
    *(float4*)&x1s[(oc0+o)*132 + px0 + 4] = make_float4(v4[4],v4[5],v4[6],v4[7]);
    *(float4*)&gx1b[(oc0+o)*HWc + px0]     = make_float4(v4[0],v4[1],v4[2],v4[3]);
    *(float4*)&gx1b[(oc0+o)*HWc + px0 + 4] = make_float4(v4[4],v4[5],v4[6],v4[7]);
  }
  __syncthreads();

  const int ocr = (t >> 5) * 4;
  const int pxr = (t & 31) * 4;
  u64p racc[4][2];
  #pragma unroll
  for (int o = 0; o < 4; o++) {
    float bv = br[ocr + o];
    u64p bp = pk(bv, bv);
    racc[o][0] = bp; racc[o][1] = bp;
  }
  #pragma unroll 4
  for (int c = 0; c < 64; c++) {
    float4 wv = *(const float4*)&wrt[c*32 + ocr];
    float4 xv = *(const float4*)&x1s[c*132 + pxr];
    u64p xp[2] = {pk(xv.x,xv.y), pk(xv.z,xv.w)};
    u64p wd[4] = {pk(wv.x,wv.x), pk(wv.y,wv.y), pk(wv.z,wv.z), pk(wv.w,wv.w)};
    #pragma unroll
    for (int o = 0; o < 4; o++) {
      fma2(racc[o][0], wd[o], xp[0]);
      fma2(racc[o][1], wd[o], xp[1]);
    }
  }
  float* gfb = g_f + (b*32)*HWc + h*Wc;
  #pragma unroll
  for (int o = 0; o < 4; o++) {
    float2 v0 = up(racc[o][0]), v1 = up(racc[o][1]);
    float4 v = make_float4(fmaxf(v0.x,0.f), fmaxf(v0.y,0.f), fmaxf(v1.x,0.f), fmaxf(v1.y,0.f));
    *(float4*)&fs[(ocr+o)*132 + pxr] = v;
    *(float4*)&gfb[(ocr+o)*HWc + pxr] = v;
  }
  __syncthreads();

  if (t < 128) {
    float mx = -1e30f, sum = 0.f;
    #pragma unroll
    for (int c = 0; c < 32; c++) {
      float v = fs[c*132 + t];
      mx = fmaxf(mx, v);
      sum += v;
    }
    g_zp[(b*2)*HWc + h*Wc + t]   = mx;
    g_zp[(b*2+1)*HWc + h*Wc + t] = sum * (1.f/32.f);
  }
}

// ---------------------------------------------------------------------------
// K2: involution (R3 version). Tile 32x2 px.
// ---------------------------------------------------------------------------
__global__ __launch_bounds__(256, 2) void k_inv(
    const float* __restrict__ ws, const float* __restrict__ bs,
    const float* __restrict__ a2p)
{
  extern __shared__ float sm[];
  float* x1h = sm;                // 64ch * 8row * 38col = 19456
  float* wss = x1h + 19456;       // 6272
  float* bss = wss + 6272;        // 196
  float* fts = bss + 196;         // 64*33
  const int t = threadIdx.x;
  const int w0 = blockIdx.x << 5;
  const int h0 = blockIdx.y << 1;
  const int b  = blockIdx.z;
  const float a2 = *a2p;

  const float* gx1b = g_x1 + (b*64)*HWc;
  for (int i = t; i < 19456; i += 256) {
    int ch = i / 304, r = i - ch*304;
    int yy = r / 38, xx = r - yy*38;
    int gh = h0 - 3 + yy, gw = w0 - 3 + xx;
    float v = 0.f;
    if ((unsigned)gh < 128u && (unsigned)gw < 128u)
      v = gx1b[ch*HWc + gh*Wc + gw];
    x1h[i] = v;
  }
  for (int i = t; i < 6272; i += 256) wss[i] = ws[i];
  if (t < 196) bss[t] = bs[t];
  const float* gfb = g_f + (b*32)*HWc;
  for (int i = t; i < 2048; i += 256) {
    int c = i >> 6, p = i & 63;
    fts[p*33 + c] = gfb[c*HWc + (h0 + (p>>5))*Wc + w0 + (p&31)];
  }
  __syncthreads();

  const int p = t & 63, j = t >> 6;
  const int py = p >> 5, px = p & 31;

  u64p fp[16];
  #pragma unroll
  for (int c2 = 0; c2 < 16; c2++)
    fp[c2] = pk(fts[p*33 + 2*c2], fts[p*33 + 2*c2 + 1]);

  float acc[16];
  #pragma unroll
  for (int ch = 0; ch < 16; ch++) acc[ch] = 0.f;

  const float* wb = wss + j*49*32;
  const float* bb = bss + j*49;
  const float* xb = x1h + (j*16)*304 + py*38 + px;

  #pragma unroll 1
  for (int dy = 0; dy < 7; dy++) {
    #pragma unroll 1
    for (int dx = 0; dx < 7; dx++) {
      const int tt = dy*7 + dx;
      const float* wr2 = wb + tt*32;
      u64p k0 = 0ull, k1 = 0ull;
      #pragma unroll
      for (int c4 = 0; c4 < 8; c4++) {
        float4 wv = *(const float4*)&wr2[c4*4];
        fma2(k0, pk(wv.x, wv.y), fp[2*c4]);
        fma2(k1, pk(wv.z, wv.w), fp[2*c4 + 1]);
      }
      float2 ka = up(k0), kb = up(k1);
      const float kwt = bb[tt] + ((ka.x + ka.y) + (kb.x + kb.y));
      const float* src = xb + dy*38 + dx;
      #pragma unroll
      for (int ch = 0; ch < 16; ch++)
        acc[ch] += kwt * src[ch*304];
    }
  }

  float* gx2b = g_x2 + (b*64 + j*16)*HWc + (h0 + py)*Wc + (w0 + px);
  #pragma unroll
  for (int ch = 0; ch < 16; ch++) {
    float v = acc[ch];
    gx2b[ch*HWc] = (v >= 0.f) ? v : a2*v;
  }
}

// ---------------------------------------------------------------------------
// K3: psec 3x3 (32->32)+PReLU (R3 version). Tile 16x8, smem weights.
// ---------------------------------------------------------------------------
__global__ __launch_bounds__(256) void k_psec1(
    const float* __restrict__ wp1, const float* __restrict__ bp1,
    const float* __restrict__ app)
{
  extern __shared__ float sm[];
  float* fh  = sm;            // 32*180 = 5760
  float* wpt = fh + 5760;     // 9216 [ci*9+tap][oc]
  const int t = threadIdx.x;
  const int w0 = blockIdx.x << 4;
  const int h0 = blockIdx.y << 3;
  const int b  = blockIdx.z;
  const float ap = *app;

  const float* gfb = g_f + (b*32)*HWc;
  for (int i = t; i < 5760; i += 256) {
    int c = i / 180, r = i - c*180;
    int yy = r / 18, xx = r - yy*18;
    int gh = h0 - 1 + yy, gw = w0 - 1 + xx;
    float v = 0.f;
    if ((unsigned)gh < 128u && (unsigned)gw < 128u)
      v = gfb[c*HWc + gh*Wc + gw];
    fh[i] = v;
  }
  for (int i = t; i < 9216; i += 256) {
    int tc = i >> 5, o = i & 31;
    wpt[i] = wp1[o*288 + tc];
  }
  __syncthreads();

  const int oc0 = (t >> 6) * 8;
  const int pg  = t & 63;
  const int py  = pg >> 3;
  const int px0 = (pg & 7) * 2;

  u64p acc[4][2];
  #pragma unroll
  for (int o2 = 0; o2 < 4; o2++) {
    u64p bp = pk(bp1[oc0 + 2*o2], bp1[oc0 + 2*o2 + 1]);
    acc[o2][0] = bp; acc[o2][1] = bp;
  }

  #pragma unroll 1
  for (int ci = 0; ci < 32; ci++) {
    #pragma unroll
    for (int tap = 0; tap < 9; tap++) {
      const int di = tap / 3, dj = tap - di*3;
      ulonglong2 wa = *(const ulonglong2*)&wpt[(ci*9 + tap)*32 + oc0];
      ulonglong2 wbv = *(const ulonglong2*)&wpt[(ci*9 + tap)*32 + oc0 + 4];
      const float* fr = &fh[ci*180 + (py + di)*18 + px0 + dj];
      u64p xd0 = pk(fr[0], fr[0]), xd1 = pk(fr[1], fr[1]);
      fma2(acc[0][0], wa.x, xd0); fma2(acc[0][1], wa.x, xd1);
      fma2(acc[1][0], wa.y, xd0); fma2(acc[1][1], wa.y, xd1);
      fma2(acc[2][0], wbv.x, xd0); fma2(acc[2][1], wbv.x, xd1);
      fma2(acc[3][0], wbv.y, xd0); fma2(acc[3][1], wbv.y, xd1);
    }
  }

  float* ghb = g_h + (b*32)*HWc + (h0 + py)*Wc + (w0 + px0);
  #pragma unroll
  for (int o2 = 0; o2 < 4; o2++) {
    float2 v0 = up(acc[o2][0]);
    float2 v1 = up(acc[o2][1]);
    float a0 = (v0.x >= 0.f) ? v0.x : ap*v0.x;
    float b0 = (v0.y >= 0.f) ? v0.y : ap*v0.y;
    float a1v = (v1.x >= 0.f) ? v1.x : ap*v1.x;
    float b1v = (v1.y >= 0.f) ? v1.y : ap*v1.y;
    *(float2*)&ghb[(oc0 + 2*o2)*HWc]     = make_float2(a0, a1v);
    *(float2*)&ghb[(oc0 + 2*o2 + 1)*HWc] = make_float2(b0, b1v);
  }
}

// ---------------------------------------------------------------------------
// K4: mma.sync (HMMA) version. One row per CTA. Single fused GEMM:
//   D[m=128 oc][n=128 px] = A[128 x 304] * B[304 x 128]
// K layout (split-bf16, attn folded into B columns):
//   0..63   : W2hi   x (x2*attn)hi
//   64..127 : W2lo   x (x2*attn)hi
//   128..191: W2hi   x (x2*attn)lo
//   192..223: Wp2hi  x h_hi
//   224..255: Wp2lo  x h_hi
//   256..287: Wp2hi  x h_lo
//   288: b2hi x attnhi; 289: b2lo x attnhi; 290: b2hi x attnlo
//   291: bp2hi x 1;     292: bp2lo x 1;     293..303: zero
// ---------------------------------------------------------------------------
#define PA 312                       // A pitch (bf16)
#define PB 136                       // B pitch (bf16)
#define A_OFF 8448
#define B_OFF (A_OFF + 128*PA*2)     // 8448 + 79872 = 88320
#define SM4_BYTES (B_OFF + 304*PB*2) // + 82688 = 171008

__device__ __forceinline__ void ldsm4(uint32_t* r, uint32_t addr) {
  asm volatile("ldmatrix.sync.aligned.m8n8.x4.shared.b16 {%0,%1,%2,%3}, [%4];"
    : "=r"(r[0]), "=r"(r[1]), "=r"(r[2]), "=r"(r[3]) : "r"(addr));
}
__device__ __forceinline__ void ldsm2t(uint32_t* r, uint32_t addr) {
  asm volatile("ldmatrix.sync.aligned.m8n8.x2.trans.shared.b16 {%0,%1}, [%2];"
    : "=r"(r[0]), "=r"(r[1]) : "r"(addr));
}
__device__ __forceinline__ void mma_bf16(float* d, const uint32_t* a, const uint32_t* bf) {
  asm volatile(
    "mma.sync.aligned.m16n8k16.row.col.f32.bf16.bf16.f32 "
    "{%0,%1,%2,%3}, {%4,%5,%6,%7}, {%8,%9}, {%0,%1,%2,%3};"
    : "+f"(d[0]), "+f"(d[1]), "+f"(d[2]), "+f"(d[3])
    : "r"(a[0]), "r"(a[1]), "r"(a[2]), "r"(a[3]), "r"(bf[0]), "r"(bf[1]));
}
__device__ __forceinline__ void bf_split(float w, __nv_bfloat16& hi, __nv_bfloat16& lo) {
  hi = __float2bfloat16(w);
  lo = __float2bfloat16(w - __bfloat162float(hi));
}

__global__ __launch_bounds__(256) void k_final_mma(
    const float* __restrict__ w2,  const float* __restrict__ b2,
    const float* __restrict__ wa,  const float* __restrict__ ba,
    const float* __restrict__ wp2, const float* __restrict__ bp2,
    float* __restrict__ out)
{
  extern __shared__ char sm4[];
  const int t = threadIdx.x;
  const int wid = t >> 5, lane = t & 31;
  const int h = blockIdx.x & 127;
  const int b = blockIdx.x >> 7;
  float* attns = (float*)(sm4);        // 128 f  [0,512)
  float* was   = (float*)(sm4 + 512);  // 98 f   [512,904)
  float* zph   = (float*)(sm4 + 912);  // 1876 f [912,8416)
  __nv_bfloat16* A = (__nv_bfloat16*)(sm4 + A_OFF);
  __nv_bfloat16* B = (__nv_bfloat16*)(sm4 + B_OFF);
  const uint32_t sbase = smem_u32(sm4);

  // stage zp halo + attn weights; zero A/B pads
  {
    const float* gzb = g_zp + (b*2)*HWc;
    for (int i = t; i < 1876; i += 256) {
      int c = i / 938, r = i - c*938;
      int yy = r / 134, xx = r - yy*134;
      int gh = h - 3 + yy, gw = xx - 3;
      float v = 0.f;
      if ((unsigned)gh < 128u && (unsigned)gw < 128u)
        v = gzb[c*HWc + gh*Wc + gw];
      zph[i] = v;
    }
    if (t < 98) was[t] = wa[t];
    uint32_t* az = (uint32_t*)A;
    for (int i = t; i < 128*PA/2; i += 256) az[i] = 0;
    uint32_t* bz = (uint32_t*)B;
    for (int i = t; i < 304*PB/2; i += 256) bz[i] = 0;
  }
  __syncthreads();

  // attention per pixel
  if (t < 128) {
    float aacc = *ba;
    #pragma unroll
    for (int dy = 0; dy < 7; dy++)
      #pragma unroll
      for (int dx = 0; dx < 7; dx++) {
        const int o1 = dy*134 + t + dx;
        aacc += was[dy*7+dx]*zph[o1] + was[49 + dy*7+dx]*zph[938 + o1];
      }
    attns[t] = 1.f / (1.f + expf(-aacc));
  }
  __syncthreads();

  // ---- fill A ----
  for (int i = t; i < 8192; i += 256) {
    int m = i >> 6, c = i & 63;
    __nv_bfloat16 hi, lo; bf_split(w2[i], hi, lo);
    A[m*PA + c]       = hi;
    A[m*PA + 64 + c]  = lo;
    A[m*PA + 128 + c] = hi;
  }
  for (int i = t; i < 4096; i += 256) {
    int m = i >> 5, c = i & 31;
    __nv_bfloat16 hi, lo; bf_split(wp2[i], hi, lo);
    A[m*PA + 192 + c] = hi;
    A[m*PA + 224 + c] = lo;
    A[m*PA + 256 + c] = hi;
  }
  if (t < 128) {
    __nv_bfloat16 hi, lo; bf_split(b2[t], hi, lo);
    A[t*PA + 288] = hi;
    A[t*PA + 289] = lo;
    A[t*PA + 290] = hi;
    bf_split(bp2[t], hi, lo);
    A[t*PA + 291] = hi;
    A[t*PA + 292] = lo;
  }

  // ---- fill B ----
  {
    const float* gx2b = g_x2 + (b*64)*HWc + h*Wc;
    for (int i = t; i < 8192; i += 256) {
      int c = i >> 7, n = i & 127;
      float y = gx2b[c*HWc + n] * attns[n];
      __nv_bfloat16 hi, lo; bf_split(y, hi, lo);
      B[c*PB + n]         = hi;
      B[(64 + c)*PB + n]  = hi;
      B[(128 + c)*PB + n] = lo;
    }
    const float* ghb = g_h + (b*32)*HWc + h*Wc;
    for (int i = t; i < 4096; i += 256) {
      int c = i >> 7, n = i & 127;
      __nv_bfloat16 hi, lo; bf_split(ghb[c*HWc + n], hi, lo);
      B[(192 + c)*PB + n] = hi;
      B[(224 + c)*PB + n] = hi;
      B[(256 + c)*PB + n] = lo;
    }
    if (t < 128) {
      __nv_bfloat16 hi, lo; bf_split(attns[t], hi, lo);
      B[288*PB + t] = hi;
      B[289*PB + t] = hi;
      B[290*PB + t] = lo;
      __nv_bfloat16 one = __float2bfloat16(1.0f);
      B[291*PB + t] = one;
      B[292*PB + t] = one;
    }
  }
  __syncthreads();

  // ---- MMA mainloop: 8 warps = 4 m-warps (32 oc) x 2 n-warps (64 px) ----
  const int mw = wid & 3, nw = wid >> 2;
  const int m_base = mw*32;
  const int n_base = nw*64;
  const uint32_t Abase = sbase + A_OFF;
  const uint32_t Bbase = sbase + B_OFF;
  const uint32_t arow = lane & 15, acolh = (lane >> 4) << 3;

  float d[2][8][4];
  #pragma unroll
  for (int mt = 0; mt < 2; mt++)
    #pragma unroll
    for (int nt = 0; nt < 8; nt++)
      #pragma unroll
      for (int q = 0; q < 4; q++) d[mt][nt][q] = 0.f;

  #pragma unroll 1
  for (int kt = 0; kt < 19; kt++) {
    const int k0 = kt*16;
    uint32_t af[2][4];
    ldsm4(af[0], Abase + (uint32_t)(((m_base      + arow)*PA + k0 + acolh) * 2));
    ldsm4(af[1], Abase + (uint32_t)(((m_base + 16 + arow)*PA + k0 + acolh) * 2));
    const uint32_t brow = Bbase + (uint32_t)(((k0 + (lane & 15))*PB + n_base) * 2);
    #pragma unroll
    for (int nt = 0; nt < 8; nt++) {
      uint32_t bf[2];
      ldsm2t(bf, brow + nt*16);
      mma_bf16(d[0][nt], af[0], bf);
      mma_bf16(d[1][nt], af[1], bf);
    }
  }

  // ---- epilogue: direct store ----
  const int r = lane >> 2, c2 = (lane & 3) * 2;
  float* ob = out + (b*128)*HWc + h*Wc;
  #pragma unroll
  for (int mt = 0; mt < 2; mt++) {
    #pragma unroll
    for (int nt = 0; nt < 8; nt++) {
      const int m = m_base + mt*16 + r;
      const int n = n_base + nt*8 + c2;
      *(float2*)&ob[m*HWc + n]       = make_float2(d[mt][nt][0], d[mt][nt][1]);
      *(float2*)&ob[(m + 8)*HWc + n] = make_float2(d[mt][nt][2], d[mt][nt][3]);
    }
  }
}

// ---------------------------------------------------------------------------
extern "C" void kernel_launch(void* const* d_in, const int* in_sizes, int n_in,
                              void* d_out, int out_size)
{
  const float* x   = (const float*)d_in[0];
  const float* w1  = (const float*)d_in[1];
  const float* b1  = (const float*)d_in[2];
  const float* a1  = (const float*)d_in[3];
  const float* wr  = (const float*)d_in[4];
  const float* br  = (const float*)d_in[5];
  const float* ws  = (const float*)d_in[6];
  const float* bs  = (const float*)d_in[7];
  const float* a2  = (const float*)d_in[8];
  const float* w2  = (const float*)d_in[9];
  const float* b2  = (const float*)d_in[10];
  const float* wa  = (const float*)d_in[11];
  const float* ba  = (const float*)d_in[12];
  const float* wp1 = (const float*)d_in[13];
  const float* bp1 = (const float*)d_in[14];
  const float* ap  = (const float*)d_in[15];
  const float* wp2 = (const float*)d_in[16];
  const float* bp2 = (const float*)d_in[17];
  float* out = (float*)d_out;

  const int s1 = 27136 * 4;   // k_front
  const int s2 = 28036 * 4;   // k_inv
  const int s3 = 14976 * 4;   // k_psec1
  const int s4 = SM4_BYTES;   // k_final_mma (~167 KB)

  cudaFuncSetAttribute(k_front,     cudaFuncAttributeMaxDynamicSharedMemorySize, s1);
  cudaFuncSetAttribute(k_inv,       cudaFuncAttributeMaxDynamicSharedMemorySize, s2);
  cudaFuncSetAttribute(k_psec1,     cudaFuncAttributeMaxDynamicSharedMemorySize, s3);
  cudaFuncSetAttribute(k_final_mma, cudaFuncAttributeMaxDynamicSharedMemorySize, s4);

  k_front<<<256, 256, s1>>>(x, w1, b1, a1, wr, br);
  k_inv  <<<dim3(4, 64, 2), 256, s2>>>(ws, bs, a2);
  k_psec1<<<dim3(8, 16, 2), 256, s3>>>(wp1, bp1, ap);
  k_final_mma<<<256, 256, s4>>>(w2, b2, wa, ba, wp2, bp2, out);
}

// round 11
// speedup vs baseline: 1.3929x; 1.1403x over previous
#include <cuda_runtime.h>
#include <cuda_bf16.h>
#include <math.h>
#include <cstdint>

#define Hc 128
#define Wc 128
#define HWc 16384

typedef unsigned long long u64p;

__device__ __forceinline__ u64p pk(float lo, float hi) {
  u64p r; asm("mov.b64 %0, {%1,%2};" : "=l"(r) : "f"(lo), "f"(hi)); return r;
}
__device__ __forceinline__ void fma2(u64p& a, u64p x, u64p y) {
  asm("fma.rn.f32x2 %0, %1, %2, %0;" : "+l"(a) : "l"(x), "l"(y));
}
__device__ __forceinline__ float2 up(u64p v) {
  float2 f; asm("mov.b64 {%0,%1}, %2;" : "=f"(f.x), "=f"(f.y) : "l"(v)); return f;
}
__device__ __forceinline__ uint32_t smem_u32(const void* p) {
  uint32_t a;
  asm("{ .reg .u64 t; cvta.to.shared.u64 t, %1; cvt.u32.u64 %0, t; }" : "=r"(a) : "l"(p));
  return a;
}

// activations scratch
__device__ float g_x1[2*64*HWc];
__device__ float g_f [2*32*HWc];
__device__ float g_zp[2*2*HWc];
__device__ float g_x2[2*64*HWc];
__device__ float g_h [2*32*HWc];
// A-matrix of the fused final GEMM, prebuilt in mma fragment layout:
// [kt(19)][mtile(8)][lane(32)][q(4)] as bf16x2 words
__device__ uint32_t g_afrag[19*8*32*4];

// ---------------------------------------------------------------------------
// K1: one row (128 px). conv1 (128->64)+PReLU -> x1 ; reduce (64->32)+ReLU -> f;
// ZPool -> zp. (R3 known-good version.)
// ---------------------------------------------------------------------------
__global__ __launch_bounds__(256, 2) void k_front(
    const float* __restrict__ x,  const float* __restrict__ w1,
    const float* __restrict__ b1, const float* __restrict__ a1p,
    const float* __restrict__ wr, const float* __restrict__ br)
{
  extern __shared__ float sm[];
  float* xs  = sm;              // 32*132
  float* w1t = xs + 4224;       // 8192  [c][oc]
  float* x1s = w1t + 8192;      // 64*132
  float* wrt = x1s + 8448;      // 2048  [c][oc]
  float* fs  = wrt + 2048;      // 32*132
  const int t = threadIdx.x;
  const int h = blockIdx.x & 127;
  const int b = blockIdx.x >> 7;
  const float a1 = *a1p;

  for (int i = t; i < 8192; i += 256) { int c = i >> 6, oc = i & 63; w1t[i] = w1[oc*128 + c]; }
  for (int i = t; i < 2048; i += 256) { int c = i >> 5, oc = i & 31; wrt[i] = wr[oc*64 + c]; }

  const int oc0 = (t >> 4) * 4;
  const int px0 = (t & 15) * 8;
  u64p acc[4][4];
  #pragma unroll
  for (int o = 0; o < 4; o++) {
    float bv = b1[oc0 + o];
    u64p bp = pk(bv, bv);
    #pragma unroll
    for (int p = 0; p < 4; p++) acc[o][p] = bp;
  }

  const float* xb = x + (b*128)*HWc + h*Wc;
  for (int cc = 0; cc < 4; cc++) {
    __syncthreads();
    for (int i = t; i < 4096; i += 256) {
      int ci = i >> 7, p = i & 127;
      xs[ci*132 + p] = xb[(cc*32 + ci)*HWc + p];
    }
    __syncthreads();
    #pragma unroll 4
    for (int ci = 0; ci < 32; ci++) {
      const int c = cc*32 + ci;
      float4 wv  = *(const float4*)&w1t[c*64 + oc0];
      float4 xa  = *(const float4*)&xs[ci*132 + px0];
      float4 xb4 = *(const float4*)&xs[ci*132 + px0 + 4];
      u64p xp[4] = {pk(xa.x,xa.y), pk(xa.z,xa.w), pk(xb4.x,xb4.y), pk(xb4.z,xb4.w)};
      u64p wd[4] = {pk(wv.x,wv.x), pk(wv.y,wv.y), pk(wv.z,wv.z), pk(wv.w,wv.w)};
      #pragma unroll
      for (int o = 0; o < 4; o++)
        #pragma unroll
        for (int p = 0; p < 4; p++)
          fma2(acc[o][p], wd[o], xp[p]);
    }
  }

  float* gx1b = g_x1 + (b*64)*HWc + h*Wc;
  #pragma unroll
  for (int o = 0; o < 4; o++) {
    float v4[8];
    #pragma unroll
    for (int p = 0; p < 4; p++) {
      float2 v = up(acc[o][p]);
      v4[2*p]   = (v.x >= 0.f) ? v.x : a1*v.x;
      v4[2*p+1] = (v.y >= 0.f) ? v.y : a1*v.y;
    }
    *(float4*)&x1s[(oc0+o)*132 + px0]     = make_float4(v4[0],v4[1],v4[2],v4[3]);
    *(float4*)&x1s[(oc0+o)*132 + px0 + 4] = make_float4(v4[4],v4[5],v4[6],v4[7]);
    *(float4*)&gx1b[(oc0+o)*HWc + px0]     = make_float4(v4[0],v4[1],v4[2],v4[3]);
    *(float4*)&gx1b[(oc0+o)*HWc + px0 + 4] = make_float4(v4[4],v4[5],v4[6],v4[7]);
  }
  __syncthreads();

  const int ocr = (t >> 5) * 4;
  const int pxr = (t & 31) * 4;
  u64p racc[4][2];
  #pragma unroll
  for (int o = 0; o < 4; o++) {
    float bv = br[ocr + o];
    u64p bp = pk(bv, bv);
    racc[o][0] = bp; racc[o][1] = bp;
  }
  #pragma unroll 4
  for (int c = 0; c < 64; c++) {
    float4 wv = *(const float4*)&wrt[c*32 + ocr];
    float4 xv = *(const float4*)&x1s[c*132 + pxr];
    u64p xp[2] = {pk(xv.x,xv.y), pk(xv.z,xv.w)};
    u64p wd[4] = {pk(wv.x,wv.x), pk(wv.y,wv.y), pk(wv.z,wv.z), pk(wv.w,wv.w)};
    #pragma unroll
    for (int o = 0; o < 4; o++) {
      fma2(racc[o][0], wd[o], xp[0]);
      fma2(racc[o][1], wd[o], xp[1]);
    }
  }
  float* gfb = g_f + (b*32)*HWc + h*Wc;
  #pragma unroll
  for (int o = 0; o < 4; o++) {
    float2 v0 = up(racc[o][0]), v1 = up(racc[o][1]);
    float4 v = make_float4(fmaxf(v0.x,0.f), fmaxf(v0.y,0.f), fmaxf(v1.x,0.f), fmaxf(v1.y,0.f));
    *(float4*)&fs[(ocr+o)*132 + pxr] = v;
    *(float4*)&gfb[(ocr+o)*HWc + pxr] = v;
  }
  __syncthreads();

  if (t < 128) {
    float mx = -1e30f, sum = 0.f;
    #pragma unroll
    for (int c = 0; c < 32; c++) {
      float v = fs[c*132 + t];
      mx = fmaxf(mx, v);
      sum += v;
    }
    g_zp[(b*2)*HWc + h*Wc + t]   = mx;
    g_zp[(b*2+1)*HWc + h*Wc + t] = sum * (1.f/32.f);
  }
}

// ---------------------------------------------------------------------------
// K2: involution (R3 version). Tile 32x2 px.
// ---------------------------------------------------------------------------
__global__ __launch_bounds__(256, 2) void k_inv(
    const float* __restrict__ ws, const float* __restrict__ bs,
    const float* __restrict__ a2p)
{
  extern __shared__ float sm[];
  float* x1h = sm;                // 64ch * 8row * 38col = 19456
  float* wss = x1h + 19456;       // 6272
  float* bss = wss + 6272;        // 196
  float* fts = bss + 196;         // 64*33
  const int t = threadIdx.x;
  const int w0 = blockIdx.x << 5;
  const int h0 = blockIdx.y << 1;
  const int b  = blockIdx.z;
  const float a2 = *a2p;

  const float* gx1b = g_x1 + (b*64)*HWc;
  for (int i = t; i < 19456; i += 256) {
    int ch = i / 304, r = i - ch*304;
    int yy = r / 38, xx = r - yy*38;
    int gh = h0 - 3 + yy, gw = w0 - 3 + xx;
    float v = 0.f;
    if ((unsigned)gh < 128u && (unsigned)gw < 128u)
      v = gx1b[ch*HWc + gh*Wc + gw];
    x1h[i] = v;
  }
  for (int i = t; i < 6272; i += 256) wss[i] = ws[i];
  if (t < 196) bss[t] = bs[t];
  const float* gfb = g_f + (b*32)*HWc;
  for (int i = t; i < 2048; i += 256) {
    int c = i >> 6, p = i & 63;
    fts[p*33 + c] = gfb[c*HWc + (h0 + (p>>5))*Wc + w0 + (p&31)];
  }
  __syncthreads();

  const int p = t & 63, j = t >> 6;
  const int py = p >> 5, px = p & 31;

  u64p fp[16];
  #pragma unroll
  for (int c2 = 0; c2 < 16; c2++)
    fp[c2] = pk(fts[p*33 + 2*c2], fts[p*33 + 2*c2 + 1]);

  float acc[16];
  #pragma unroll
  for (int ch = 0; ch < 16; ch++) acc[ch] = 0.f;

  const float* wb = wss + j*49*32;
  const float* bb = bss + j*49;
  const float* xb = x1h + (j*16)*304 + py*38 + px;

  #pragma unroll 1
  for (int dy = 0; dy < 7; dy++) {
    #pragma unroll 1
    for (int dx = 0; dx < 7; dx++) {
      const int tt = dy*7 + dx;
      const float* wr2 = wb + tt*32;
      u64p k0 = 0ull, k1 = 0ull;
      #pragma unroll
      for (int c4 = 0; c4 < 8; c4++) {
        float4 wv = *(const float4*)&wr2[c4*4];
        fma2(k0, pk(wv.x, wv.y), fp[2*c4]);
        fma2(k1, pk(wv.z, wv.w), fp[2*c4 + 1]);
      }
      float2 ka = up(k0), kb = up(k1);
      const float kwt = bb[tt] + ((ka.x + ka.y) + (kb.x + kb.y));
      const float* src = xb + dy*38 + dx;
      #pragma unroll
      for (int ch = 0; ch < 16; ch++)
        acc[ch] += kwt * src[ch*304];
    }
  }

  float* gx2b = g_x2 + (b*64 + j*16)*HWc + (h0 + py)*Wc + (w0 + px);
  #pragma unroll
  for (int ch = 0; ch < 16; ch++) {
    float v = acc[ch];
    gx2b[ch*HWc] = (v >= 0.f) ? v : a2*v;
  }
}

// ---------------------------------------------------------------------------
// K3: psec 3x3 (32->32)+PReLU (R3 version). Tile 16x8, smem weights.
// ---------------------------------------------------------------------------
__global__ __launch_bounds__(256) void k_psec1(
    const float* __restrict__ wp1, const float* __restrict__ bp1,
    const float* __restrict__ app)
{
  extern __shared__ float sm[];
  float* fh  = sm;            // 32*180 = 5760
  float* wpt = fh + 5760;     // 9216 [ci*9+tap][oc]
  const int t = threadIdx.x;
  const int w0 = blockIdx.x << 4;
  const int h0 = blockIdx.y << 3;
  const int b  = blockIdx.z;
  const float ap = *app;

  const float* gfb = g_f + (b*32)*HWc;
  for (int i = t; i < 5760; i += 256) {
    int c = i / 180, r = i - c*180;
    int yy = r / 18, xx = r - yy*18;
    int gh = h0 - 1 + yy, gw = w0 - 1 + xx;
    float v = 0.f;
    if ((unsigned)gh < 128u && (unsigned)gw < 128u)
      v = gfb[c*HWc + gh*Wc + gw];
    fh[i] = v;
  }
  for (int i = t; i < 9216; i += 256) {
    int tc = i >> 5, o = i & 31;
    wpt[i] = wp1[o*288 + tc];
  }
  __syncthreads();

  const int oc0 = (t >> 6) * 8;
  const int pg  = t & 63;
  const int py  = pg >> 3;
  const int px0 = (pg & 7) * 2;

  u64p acc[4][2];
  #pragma unroll
  for (int o2 = 0; o2 < 4; o2++) {
    u64p bp = pk(bp1[oc0 + 2*o2], bp1[oc0 + 2*o2 + 1]);
    acc[o2][0] = bp; acc[o2][1] = bp;
  }

  #pragma unroll 1
  for (int ci = 0; ci < 32; ci++) {
    #pragma unroll
    for (int tap = 0; tap < 9; tap++) {
      const int di = tap / 3, dj = tap - di*3;
      ulonglong2 wa = *(const ulonglong2*)&wpt[(ci*9 + tap)*32 + oc0];
      ulonglong2 wbv = *(const ulonglong2*)&wpt[(ci*9 + tap)*32 + oc0 + 4];
      const float* fr = &fh[ci*180 + (py + di)*18 + px0 + dj];
      u64p xd0 = pk(fr[0], fr[0]), xd1 = pk(fr[1], fr[1]);
      fma2(acc[0][0], wa.x, xd0); fma2(acc[0][1], wa.x, xd1);
      fma2(acc[1][0], wa.y, xd0); fma2(acc[1][1], wa.y, xd1);
      fma2(acc[2][0], wbv.x, xd0); fma2(acc[2][1], wbv.x, xd1);
      fma2(acc[3][0], wbv.y, xd0); fma2(acc[3][1], wbv.y, xd1);
    }
  }

  float* ghb = g_h + (b*32)*HWc + (h0 + py)*Wc + (w0 + px0);
  #pragma unroll
  for (int o2 = 0; o2 < 4; o2++) {
    float2 v0 = up(acc[o2][0]);
    float2 v1 = up(acc[o2][1]);
    float a0 = (v0.x >= 0.f) ? v0.x : ap*v0.x;
    float b0 = (v0.y >= 0.f) ? v0.y : ap*v0.y;
    float a1v = (v1.x >= 0.f) ? v1.x : ap*v1.x;
    float b1v = (v1.y >= 0.f) ? v1.y : ap*v1.y;
    *(float2*)&ghb[(oc0 + 2*o2)*HWc]     = make_float2(a0, a1v);
    *(float2*)&ghb[(oc0 + 2*o2 + 1)*HWc] = make_float2(b0, b1v);
  }
}

// ---------------------------------------------------------------------------
// K-prep: build A fragments of the fused final GEMM (K' = 304):
//   0..63   W2hi | 64..127 W2lo | 128..191 W2hi
//   192..223 Wp2hi | 224..255 Wp2lo | 256..287 Wp2hi
//   288 b2hi | 289 b2lo | 290 b2hi | 291 bp2hi | 292 bp2lo | 293.. 0
// canonical m16n8k16 A fragment: q -> (row+8*(q&1), col+8*(q>>1)),
// lane -> row=lane>>2, col=2*(lane&3). Stored as bf16x2 (col, col+1).
// ---------------------------------------------------------------------------
__device__ __forceinline__ __nv_bfloat16 aval(int m, int k,
    const float* __restrict__ w2, const float* __restrict__ b2,
    const float* __restrict__ wp2, const float* __restrict__ bp2)
{
  float v; bool lo = false;
  if      (k < 64)  { v = w2[m*64 + k]; }
  else if (k < 128) { v = w2[m*64 + k - 64]; lo = true; }
  else if (k < 192) { v = w2[m*64 + k - 128]; }
  else if (k < 224) { v = wp2[m*32 + k - 192]; }
  else if (k < 256) { v = wp2[m*32 + k - 224]; lo = true; }
  else if (k < 288) { v = wp2[m*32 + k - 256]; }
  else if (k == 288) { v = b2[m]; }
  else if (k == 289) { v = b2[m]; lo = true; }
  else if (k == 290) { v = b2[m]; }
  else if (k == 291) { v = bp2[m]; }
  else if (k == 292) { v = bp2[m]; lo = true; }
  else return __float2bfloat16(0.f);
  __nv_bfloat16 hi = __float2bfloat16(v);
  if (!lo) return hi;
  return __float2bfloat16(v - __bfloat162float(hi));
}

__global__ void k_prep_afrag(const float* __restrict__ w2,  const float* __restrict__ b2,
                             const float* __restrict__ wp2, const float* __restrict__ bp2)
{
  int idx = blockIdx.x*256 + threadIdx.x;
  if (idx >= 19456) return;
  int q    = idx & 3;
  int lane = (idx >> 2) & 31;
  int mt   = (idx >> 7) & 7;
  int kt   = idx >> 10;
  int m = mt*16 + (lane >> 2) + ((q & 1) << 3);
  int c = kt*16 + ((lane & 3) << 1) + ((q >> 1) << 3);
  __nv_bfloat16 v0 = aval(m, c,     w2, b2, wp2, bp2);
  __nv_bfloat16 v1 = aval(m, c + 1, w2, b2, wp2, bp2);
  g_afrag[idx] = (uint32_t)__bfloat16_as_ushort(v0)
               | ((uint32_t)__bfloat16_as_ushort(v1) << 16);
}

// ---------------------------------------------------------------------------
// K4: HMMA final. D[128 oc][128 px] = A[128x304] * B[304x128].
// A fragments from gmem (L2-resident); B (activations, attn folded) in smem.
// ---------------------------------------------------------------------------
#define PB 136
#define B_OFF 8448
#define SM4_BYTES (B_OFF + 304*PB*2)   // 8448 + 82688 = 91136

__device__ __forceinline__ void ldsm2t(uint32_t* r, uint32_t addr) {
  asm volatile("ldmatrix.sync.aligned.m8n8.x2.trans.shared.b16 {%0,%1}, [%2];"
    : "=r"(r[0]), "=r"(r[1]) : "r"(addr));
}
__device__ __forceinline__ void mma_bf16(float* d, const uint32_t* a, const uint32_t* bf) {
  asm volatile(
    "mma.sync.aligned.m16n8k16.row.col.f32.bf16.bf16.f32 "
    "{%0,%1,%2,%3}, {%4,%5,%6,%7}, {%8,%9}, {%0,%1,%2,%3};"
    : "+f"(d[0]), "+f"(d[1]), "+f"(d[2]), "+f"(d[3])
    : "r"(a[0]), "r"(a[1]), "r"(a[2]), "r"(a[3]), "r"(bf[0]), "r"(bf[1]));
}
__device__ __forceinline__ void bf_split(float w, __nv_bfloat16& hi, __nv_bfloat16& lo) {
  hi = __float2bfloat16(w);
  lo = __float2bfloat16(w - __bfloat162float(hi));
}
__device__ __forceinline__ uint32_t pk2bf(__nv_bfloat16 a, __nv_bfloat16 b) {
  return (uint32_t)__bfloat16_as_ushort(a) | ((uint32_t)__bfloat16_as_ushort(b) << 16);
}

__global__ __launch_bounds__(256, 2) void k_final_mma(
    const float* __restrict__ wa, const float* __restrict__ ba,
    float* __restrict__ out)
{
  extern __shared__ char sm4[];
  const int t = threadIdx.x;
  const int wid = t >> 5, lane = t & 31;
  const int h = blockIdx.x & 127;
  const int b = blockIdx.x >> 7;
  float* attns = (float*)(sm4);        // 128 f  [0,512)
  float* was   = (float*)(sm4 + 512);  // 98 f
  float* zph   = (float*)(sm4 + 912);  // 1876 f -> ends 8416
  __nv_bfloat16* B = (__nv_bfloat16*)(sm4 + B_OFF);
  const uint32_t sbase = smem_u32(sm4);

  // stage zp halo + attn weights
  {
    const float* gzb = g_zp + (b*2)*HWc;
    for (int i = t; i < 1876; i += 256) {
      int c = i / 938, r = i - c*938;
      int yy = r / 134, xx = r - yy*134;
      int gh = h - 3 + yy, gw = xx - 3;
      float v = 0.f;
      if ((unsigned)gh < 128u && (unsigned)gw < 128u)
        v = gzb[c*HWc + gh*Wc + gw];
      zph[i] = v;
    }
    if (t < 98) was[t] = wa[t];
  }
  __syncthreads();

  // attention per pixel
  if (t < 128) {
    float aacc = *ba;
    #pragma unroll
    for (int dy = 0; dy < 7; dy++)
      #pragma unroll
      for (int dx = 0; dx < 7; dx++) {
        const int o1 = dy*134 + t + dx;
        aacc += was[dy*7+dx]*zph[o1] + was[49 + dy*7+dx]*zph[938 + o1];
      }
    attns[t] = 1.f / (1.f + expf(-aacc));
  }
  __syncthreads();

  // ---- fill B (packed bf16x2 stores, 2 px per thread-iter) ----
  {
    const float* gx2b = g_x2 + (b*64)*HWc + h*Wc;
    for (int i = t; i < 4096; i += 256) {
      int c = i >> 6, n2 = (i & 63) * 2;
      float2 xv = *(const float2*)&gx2b[c*HWc + n2];
      float y0 = xv.x * attns[n2], y1 = xv.y * attns[n2+1];
      __nv_bfloat16 h0, l0, h1, l1; bf_split(y0, h0, l0); bf_split(y1, h1, l1);
      uint32_t hh = pk2bf(h0, h1), ll = pk2bf(l0, l1);
      *(uint32_t*)&B[c*PB + n2]         = hh;
      *(uint32_t*)&B[(64 + c)*PB + n2]  = hh;
      *(uint32_t*)&B[(128 + c)*PB + n2] = ll;
    }
    const float* ghb = g_h + (b*32)*HWc + h*Wc;
    for (int i = t; i < 2048; i += 256) {
      int c = i >> 6, n2 = (i & 63) * 2;
      float2 hv = *(const float2*)&ghb[c*HWc + n2];
      __nv_bfloat16 h0, l0, h1, l1; bf_split(hv.x, h0, l0); bf_split(hv.y, h1, l1);
      uint32_t hh = pk2bf(h0, h1), ll = pk2bf(l0, l1);
      *(uint32_t*)&B[(192 + c)*PB + n2] = hh;
      *(uint32_t*)&B[(224 + c)*PB + n2] = hh;
      *(uint32_t*)&B[(256 + c)*PB + n2] = ll;
    }
    if (t < 64) {
      int n2 = t*2;
      __nv_bfloat16 h0, l0, h1, l1;
      bf_split(attns[n2], h0, l0); bf_split(attns[n2+1], h1, l1);
      uint32_t hh = pk2bf(h0, h1), ll = pk2bf(l0, l1);
      *(uint32_t*)&B[288*PB + n2] = hh;
      *(uint32_t*)&B[289*PB + n2] = hh;
      *(uint32_t*)&B[290*PB + n2] = ll;
      __nv_bfloat16 one = __float2bfloat16(1.0f);
      uint32_t oo = pk2bf(one, one);
      *(uint32_t*)&B[291*PB + n2] = oo;
      *(uint32_t*)&B[292*PB + n2] = oo;
    }
    // zero only the read tail rows 293..303 (cols 0..127)
    for (int i = t; i < 11*64; i += 256) {
      int r = 293 + (i >> 6), n2 = (i & 63) * 2;
      *(uint32_t*)&B[r*PB + n2] = 0u;
    }
  }
  __syncthreads();

  // ---- MMA mainloop: 8 warps = 4 m-warps (32 oc) x 2 n-warps (64 px) ----
  const int mw = wid & 3, nw = wid >> 2;
  const uint32_t Bbase = sbase + B_OFF;
  const uint4* __restrict__ afp = (const uint4*)g_afrag;

  float d[2][8][4];
  #pragma unroll
  for (int mt = 0; mt < 2; mt++)
    #pragma unroll
    for (int nt = 0; nt < 8; nt++)
      #pragma unroll
      for (int q = 0; q < 4; q++) d[mt][nt][q] = 0.f;

  uint4 a0 = afp[(0*8 + mw*2 + 0)*32 + lane];
  uint4 a1 = afp[(0*8 + mw*2 + 1)*32 + lane];

  #pragma unroll 1
  for (int kt = 0; kt < 19; kt++) {
    uint4 na0, na1;
    if (kt < 18) {
      na0 = afp[((kt+1)*8 + mw*2 + 0)*32 + lane];
      na1 = afp[((kt+1)*8 + mw*2 + 1)*32 + lane];
    }
    const uint32_t brow = Bbase + (uint32_t)(((kt*16 + (lane & 15))*PB + nw*64) * 2);
    #pragma unroll
    for (int nt = 0; nt < 8; nt++) {
      uint32_t bf[2];
      ldsm2t(bf, brow + nt*16);
      mma_bf16(d[0][nt], (const uint32_t*)&a0, bf);
      mma_bf16(d[1][nt], (const uint32_t*)&a1, bf);
    }
    a0 = na0; a1 = na1;
  }

  // ---- epilogue: direct store ----
  const int r = lane >> 2, c2 = (lane & 3) * 2;
  const int m_base = mw*32, n_base = nw*64;
  float* ob = out + (b*128)*HWc + h*Wc;
  #pragma unroll
  for (int mt = 0; mt < 2; mt++) {
    #pragma unroll
    for (int nt = 0; nt < 8; nt++) {
      const int m = m_base + mt*16 + r;
      const int n = n_base + nt*8 + c2;
      *(float2*)&ob[m*HWc + n]       = make_float2(d[mt][nt][0], d[mt][nt][1]);
      *(float2*)&ob[(m + 8)*HWc + n] = make_float2(d[mt][nt][2], d[mt][nt][3]);
    }
  }
}

// ---------------------------------------------------------------------------
extern "C" void kernel_launch(void* const* d_in, const int* in_sizes, int n_in,
                              void* d_out, int out_size)
{
  const float* x   = (const float*)d_in[0];
  const float* w1  = (const float*)d_in[1];
  const float* b1  = (const float*)d_in[2];
  const float* a1  = (const float*)d_in[3];
  const float* wr  = (const float*)d_in[4];
  const float* br  = (const float*)d_in[5];
  const float* ws  = (const float*)d_in[6];
  const float* bs  = (const float*)d_in[7];
  const float* a2  = (const float*)d_in[8];
  const float* w2  = (const float*)d_in[9];
  const float* b2  = (const float*)d_in[10];
  const float* wa  = (const float*)d_in[11];
  const float* ba  = (const float*)d_in[12];
  const float* wp1 = (const float*)d_in[13];
  const float* bp1 = (const float*)d_in[14];
  const float* ap  = (const float*)d_in[15];
  const float* wp2 = (const float*)d_in[16];
  const float* bp2 = (const float*)d_in[17];
  float* out = (float*)d_out;

  const int s1 = 27136 * 4;   // k_front
  const int s2 = 28036 * 4;   // k_inv
  const int s3 = 14976 * 4;   // k_psec1
  const int s4 = SM4_BYTES;   // k_final_mma (~89 KB -> 2 CTAs/SM)

  cudaFuncSetAttribute(k_front,     cudaFuncAttributeMaxDynamicSharedMemorySize, s1);
  cudaFuncSetAttribute(k_inv,       cudaFuncAttributeMaxDynamicSharedMemorySize, s2);
  cudaFuncSetAttribute(k_psec1,     cudaFuncAttributeMaxDynamicSharedMemorySize, s3);
  cudaFuncSetAttribute(k_final_mma, cudaFuncAttributeMaxDynamicSharedMemorySize, s4);

  k_prep_afrag<<<76, 256>>>(w2, b2, wp2, bp2);
  k_front<<<256, 256, s1>>>(x, w1, b1, a1, wr, br);
  k_inv  <<<dim3(4, 64, 2), 256, s2>>>(ws, bs, a2);
  k_psec1<<<dim3(8, 16, 2), 256, s3>>>(wp1, bp1, ap);
  k_final_mma<<<256, 256, s4>>>(wa, ba, out);
}

// round 12
// speedup vs baseline: 1.4838x; 1.0652x over previous
#include <cuda_runtime.h>
#include <cuda_bf16.h>
#include <math.h>
#include <cstdint>

#define Hc 128
#define Wc 128
#define HWc 16384

typedef unsigned long long u64p;

__device__ __forceinline__ u64p pk(float lo, float hi) {
  u64p r; asm("mov.b64 %0, {%1,%2};" : "=l"(r) : "f"(lo), "f"(hi)); return r;
}
__device__ __forceinline__ void fma2(u64p& a, u64p x, u64p y) {
  asm("fma.rn.f32x2 %0, %1, %2, %0;" : "+l"(a) : "l"(x), "l"(y));
}
__device__ __forceinline__ float2 up(u64p v) {
  float2 f; asm("mov.b64 {%0,%1}, %2;" : "=f"(f.x), "=f"(f.y) : "l"(v)); return f;
}
__device__ __forceinline__ uint32_t smem_u32(const void* p) {
  uint32_t a;
  asm("{ .reg .u64 t; cvta.to.shared.u64 t, %1; cvt.u32.u64 %0, t; }" : "=r"(a) : "l"(p));
  return a;
}

// activations scratch
__device__ float g_x1[2*64*HWc];
__device__ float g_f [2*32*HWc];
__device__ float g_zp[2*2*HWc];
__device__ float g_x2[2*64*HWc];
__device__ float g_h [2*32*HWc];
// Prebuilt A fragments (canonical m16n8k16 layout, bf16x2 words):
__device__ uint32_t g_afrag [19*8*32*4];   // final fused GEMM  (K'=304, M=128)
__device__ uint32_t g_afrag1[25*4*32*4];   // conv1   (K'=400, M=64)
__device__ uint32_t g_afrag2[13*2*32*4];   // reduce  (K'=208, M=32)

// ---------------------------------------------------------------------------
// common mma helpers
// ---------------------------------------------------------------------------
__device__ __forceinline__ void ldsm2t(uint32_t* r, uint32_t addr) {
  asm volatile("ldmatrix.sync.aligned.m8n8.x2.trans.shared.b16 {%0,%1}, [%2];"
    : "=r"(r[0]), "=r"(r[1]) : "r"(addr));
}
__device__ __forceinline__ void mma_bf16(float* d, const uint32_t* a, const uint32_t* bf) {
  asm volatile(
    "mma.sync.aligned.m16n8k16.row.col.f32.bf16.bf16.f32 "
    "{%0,%1,%2,%3}, {%4,%5,%6,%7}, {%8,%9}, {%0,%1,%2,%3};"
    : "+f"(d[0]), "+f"(d[1]), "+f"(d[2]), "+f"(d[3])
    : "r"(a[0]), "r"(a[1]), "r"(a[2]), "r"(a[3]), "r"(bf[0]), "r"(bf[1]));
}
__device__ __forceinline__ void bf_split(float w, __nv_bfloat16& hi, __nv_bfloat16& lo) {
  hi = __float2bfloat16(w);
  lo = __float2bfloat16(w - __bfloat162float(hi));
}
__device__ __forceinline__ uint32_t pk2bf(__nv_bfloat16 a, __nv_bfloat16 b) {
  return (uint32_t)__bfloat16_as_ushort(a) | ((uint32_t)__bfloat16_as_ushort(b) << 16);
}

// ---------------------------------------------------------------------------
// K-prep: build all A-fragment tables.
// final GEMM A (K'=304): 0..63 W2hi | 64..127 W2lo | 128..191 W2hi |
//   192..223 Wp2hi | 224..255 Wp2lo | 256..287 Wp2hi |
//   288 b2hi 289 b2lo 290 b2hi | 291 bp2hi 292 bp2lo | pad 0
// conv1 A (K'=400): 0..127 W1hi | 128..255 W1lo | 256..383 W1hi |
//   384 b1hi 385 b1lo | pad 0
// reduce A (K'=208): 0..63 Wrhi | 64..127 Wrlo | 128..191 Wrhi |
//   192 brhi 193 brlo | pad 0
// ---------------------------------------------------------------------------
__device__ __forceinline__ __nv_bfloat16 hi_or_lo(float v, bool lo) {
  __nv_bfloat16 hi = __float2bfloat16(v);
  if (!lo) return hi;
  return __float2bfloat16(v - __bfloat162float(hi));
}
__device__ __forceinline__ __nv_bfloat16 aval_fin(int m, int k,
    const float* w2, const float* b2, const float* wp2, const float* bp2)
{
  if      (k < 64)  return hi_or_lo(w2[m*64 + k], false);
  else if (k < 128) return hi_or_lo(w2[m*64 + k - 64], true);
  else if (k < 192) return hi_or_lo(w2[m*64 + k - 128], false);
  else if (k < 224) return hi_or_lo(wp2[m*32 + k - 192], false);
  else if (k < 256) return hi_or_lo(wp2[m*32 + k - 224], true);
  else if (k < 288) return hi_or_lo(wp2[m*32 + k - 256], false);
  else if (k == 288) return hi_or_lo(b2[m], false);
  else if (k == 289) return hi_or_lo(b2[m], true);
  else if (k == 290) return hi_or_lo(b2[m], false);
  else if (k == 291) return hi_or_lo(bp2[m], false);
  else if (k == 292) return hi_or_lo(bp2[m], true);
  return __float2bfloat16(0.f);
}
__device__ __forceinline__ __nv_bfloat16 aval_c1(int m, int k,
    const float* w1, const float* b1)
{
  if      (k < 128) return hi_or_lo(w1[m*128 + k], false);
  else if (k < 256) return hi_or_lo(w1[m*128 + k - 128], true);
  else if (k < 384) return hi_or_lo(w1[m*128 + k - 256], false);
  else if (k == 384) return hi_or_lo(b1[m], false);
  else if (k == 385) return hi_or_lo(b1[m], true);
  return __float2bfloat16(0.f);
}
__device__ __forceinline__ __nv_bfloat16 aval_rd(int m, int k,
    const float* wr, const float* br)
{
  if      (k < 64)  return hi_or_lo(wr[m*64 + k], false);
  else if (k < 128) return hi_or_lo(wr[m*64 + k - 64], true);
  else if (k < 192) return hi_or_lo(wr[m*64 + k - 128], false);
  else if (k == 192) return hi_or_lo(br[m], false);
  else if (k == 193) return hi_or_lo(br[m], true);
  return __float2bfloat16(0.f);
}

__global__ void k_prep_afrag(
    const float* __restrict__ w2,  const float* __restrict__ b2,
    const float* __restrict__ wp2, const float* __restrict__ bp2,
    const float* __restrict__ w1,  const float* __restrict__ b1,
    const float* __restrict__ wr,  const float* __restrict__ br)
{
  int idx = blockIdx.x*256 + threadIdx.x;
  if (idx < 19456) {
    int q = idx & 3, lane = (idx >> 2) & 31, mt = (idx >> 7) & 7, kt = idx >> 10;
    int m = mt*16 + (lane >> 2) + ((q & 1) << 3);
    int c = kt*16 + ((lane & 3) << 1) + ((q >> 1) << 3);
    g_afrag[idx] = pk2bf(aval_fin(m, c, w2, b2, wp2, bp2),
                         aval_fin(m, c+1, w2, b2, wp2, bp2));
    return;
  }
  idx -= 19456;
  if (idx < 12800) {
    int q = idx & 3, lane = (idx >> 2) & 31, mt = (idx >> 7) & 3, kt = idx >> 9;
    int m = mt*16 + (lane >> 2) + ((q & 1) << 3);
    int c = kt*16 + ((lane & 3) << 1) + ((q >> 1) << 3);
    g_afrag1[idx] = pk2bf(aval_c1(m, c, w1, b1), aval_c1(m, c+1, w1, b1));
    return;
  }
  idx -= 12800;
  if (idx < 3328) {
    int q = idx & 3, lane = (idx >> 2) & 31, mt = (idx >> 7) & 1, kt = idx >> 8;
    int m = mt*16 + (lane >> 2) + ((q & 1) << 3);
    int c = kt*16 + ((lane & 3) << 1) + ((q >> 1) << 3);
    g_afrag2[idx] = pk2bf(aval_rd(m, c, wr, br), aval_rd(m, c+1, wr, br));
  }
}

// ---------------------------------------------------------------------------
// K1 (NEW, HMMA): half-row (64 px).
// GEMM1: x1 = prelu(W1 x + b1)  [M=64, K'=400]
// GEMM2: f = relu(Wr x1 + br)   [M=32, K'=208], then ZPool.
// B2 overlays B1; x1 split built straight from GEMM1 registers.
// ---------------------------------------------------------------------------
#define PB1 72                    // B pitch (bf16): 144 B rows
#define FS_OFF 0                  // fs float[32*68] = 8704 B
#define B1F_OFF 8704              // 400 rows * 144 B = 57600 -> end 66304
#define SMF_BYTES 66304

__global__ __launch_bounds__(256, 3) void k_front_mma(
    const float* __restrict__ x, const float* __restrict__ a1p,
    float* __restrict__ dummy)
{
  extern __shared__ char smf[];
  const int t = threadIdx.x;
  const int wid = t >> 5, lane = t & 31;
  const int h  = blockIdx.x;
  const int p0 = blockIdx.y * 64;
  const int b  = blockIdx.z;
  const float a1 = *a1p;
  float* fs = (float*)(smf + FS_OFF);
  __nv_bfloat16* B = (__nv_bfloat16*)(smf + B1F_OFF);
  const uint32_t Bbase = smem_u32(smf) + B1F_OFF;

  // ---- build B1 = x split (rows: 0..127 hi | 128..255 hi | 256..383 lo) ----
  {
    const float* xb = x + (b*128)*HWc + h*Wc + p0;
    for (int i = t; i < 4096; i += 256) {
      int c = i >> 5, n2 = (i & 31) * 2;
      float2 xv = *(const float2*)&xb[c*HWc + n2];
      __nv_bfloat16 h0, l0, h1, l1; bf_split(xv.x, h0, l0); bf_split(xv.y, h1, l1);
      uint32_t hh = pk2bf(h0, h1), ll = pk2bf(l0, l1);
      *(uint32_t*)&B[c*PB1 + n2]         = hh;
      *(uint32_t*)&B[(128 + c)*PB1 + n2] = hh;
      *(uint32_t*)&B[(256 + c)*PB1 + n2] = ll;
    }
    __nv_bfloat16 one = __float2bfloat16(1.0f);
    uint32_t oo = pk2bf(one, one);
    for (int i = t; i < 512; i += 256) {       // rows 384..399
      int r = 384 + (i >> 5), n2 = (i & 31) * 2;
      *(uint32_t*)&B[r*PB1 + n2] = (r < 386) ? oo : 0u;
    }
  }
  __syncthreads();

  // ---- GEMM1: M=64 (4 mt), N=64. warp = 1 mt x 4 nt(32 px) ----
  const int mw = wid & 3, nw = wid >> 2;
  const uint4* __restrict__ afp1 = (const uint4*)g_afrag1;
  float d[4][4];
  #pragma unroll
  for (int nt = 0; nt < 4; nt++)
    #pragma unroll
    for (int q = 0; q < 4; q++) d[nt][q] = 0.f;

  uint4 a0 = afp1[(0*4 + mw)*32 + lane];
  #pragma unroll 1
  for (int kt = 0; kt < 25; kt++) {
    uint4 na;
    if (kt < 24) na = afp1[((kt+1)*4 + mw)*32 + lane];
    const uint32_t brow = Bbase + (uint32_t)(((kt*16 + (lane & 15))*PB1 + nw*32) * 2);
    #pragma unroll
    for (int nt = 0; nt < 4; nt++) {
      uint32_t bf[2];
      ldsm2t(bf, brow + nt*16);
      mma_bf16(d[nt], (const uint32_t*)&a0, bf);
    }
    a0 = na;
  }
  __syncthreads();   // everyone done reading B1 before overlaying with B2

  // ---- epilogue1: PReLU in regs -> g_x1 + B2 (x1 split) ----
  {
    const int r = lane >> 2, c2 = (lane & 3) * 2;
    float* gx1b = g_x1 + (b*64)*HWc + h*Wc + p0;
    #pragma unroll
    for (int nt = 0; nt < 4; nt++) {
      const int n = nw*32 + nt*8 + c2;
      #pragma unroll
      for (int half = 0; half < 2; half++) {
        const int m = mw*16 + r + half*8;
        float v0 = d[nt][half*2], v1 = d[nt][half*2 + 1];
        v0 = (v0 >= 0.f) ? v0 : a1*v0;
        v1 = (v1 >= 0.f) ? v1 : a1*v1;
        *(float2*)&gx1b[m*HWc + n] = make_float2(v0, v1);
        __nv_bfloat16 h0, l0, h1, l1; bf_split(v0, h0, l0); bf_split(v1, h1, l1);
        uint32_t hh = pk2bf(h0, h1), ll = pk2bf(l0, l1);
        *(uint32_t*)&B[m*PB1 + n]         = hh;
        *(uint32_t*)&B[(64 + m)*PB1 + n]  = hh;
        *(uint32_t*)&B[(128 + m)*PB1 + n] = ll;
      }
    }
    __nv_bfloat16 one = __float2bfloat16(1.0f);
    uint32_t oo = pk2bf(one, one);
    for (int i = t; i < 512; i += 256) {       // rows 192..207
      int rr = 192 + (i >> 5), n2 = (i & 31) * 2;
      *(uint32_t*)&B[rr*PB1 + n2] = (rr < 194) ? oo : 0u;
    }
  }
  __syncthreads();

  // ---- GEMM2: M=32 (2 mt), N=64. warp = 1 mt x 2 nt(16 px) ----
  const int mw2 = wid & 1, nw2 = wid >> 1;     // nw2 in 0..3
  const uint4* __restrict__ afp2 = (const uint4*)g_afrag2;
  float d2[2][4];
  #pragma unroll
  for (int nt = 0; nt < 2; nt++)
    #pragma unroll
    for (int q = 0; q < 4; q++) d2[nt][q] = 0.f;

  uint4 a2 = afp2[(0*2 + mw2)*32 + lane];
  #pragma unroll 1
  for (int kt = 0; kt < 13; kt++) {
    uint4 na;
    if (kt < 12) na = afp2[((kt+1)*2 + mw2)*32 + lane];
    const uint32_t brow = Bbase + (uint32_t)(((kt*16 + (lane & 15))*PB1 + nw2*16) * 2);
    #pragma unroll
    for (int nt = 0; nt < 2; nt++) {
      uint32_t bf[2];
      ldsm2t(bf, brow + nt*16);
      mma_bf16(d2[nt], (const uint32_t*)&a2, bf);
    }
    a2 = na;
  }

  // ---- epilogue2: ReLU -> g_f + fs ----
  {
    const int r = lane >> 2, c2 = (lane & 3) * 2;
    float* gfb = g_f + (b*32)*HWc + h*Wc + p0;
    #pragma unroll
    for (int nt = 0; nt < 2; nt++) {
      const int n = nw2*16 + nt*8 + c2;
      #pragma unroll
      for (int half = 0; half < 2; half++) {
        const int m = mw2*16 + r + half*8;
        float v0 = fmaxf(d2[nt][half*2], 0.f);
        float v1 = fmaxf(d2[nt][half*2 + 1], 0.f);
        *(float2*)&gfb[m*HWc + n] = make_float2(v0, v1);
        *(float2*)&fs[m*68 + n]   = make_float2(v0, v1);
      }
    }
  }
  __syncthreads();

  if (t < 64) {
    float mx = -1e30f, sum = 0.f;
    #pragma unroll
    for (int c = 0; c < 32; c++) {
      float v = fs[c*68 + t];
      mx = fmaxf(mx, v);
      sum += v;
    }
    g_zp[(b*2)*HWc + h*Wc + p0 + t]   = mx;
    g_zp[(b*2+1)*HWc + h*Wc + p0 + t] = sum * (1.f/32.f);
  }
}

// ---------------------------------------------------------------------------
// K2: involution (R3 version). Tile 32x2 px.
// ---------------------------------------------------------------------------
__global__ __launch_bounds__(256, 2) void k_inv(
    const float* __restrict__ ws, const float* __restrict__ bs,
    const float* __restrict__ a2p)
{
  extern __shared__ float sm[];
  float* x1h = sm;                // 64ch * 8row * 38col = 19456
  float* wss = x1h + 19456;       // 6272
  float* bss = wss + 6272;        // 196
  float* fts = bss + 196;         // 64*33
  const int t = threadIdx.x;
  const int w0 = blockIdx.x << 5;
  const int h0 = blockIdx.y << 1;
  const int b  = blockIdx.z;
  const float a2 = *a2p;

  const float* gx1b = g_x1 + (b*64)*HWc;
  for (int i = t; i < 19456; i += 256) {
    int ch = i / 304, r = i - ch*304;
    int yy = r / 38, xx = r - yy*38;
    int gh = h0 - 3 + yy, gw = w0 - 3 + xx;
    float v = 0.f;
    if ((unsigned)gh < 128u && (unsigned)gw < 128u)
      v = gx1b[ch*HWc + gh*Wc + gw];
    x1h[i] = v;
  }
  for (int i = t; i < 6272; i += 256) wss[i] = ws[i];
  if (t < 196) bss[t] = bs[t];
  const float* gfb = g_f + (b*32)*HWc;
  for (int i = t; i < 2048; i += 256) {
    int c = i >> 6, p = i & 63;
    fts[p*33 + c] = gfb[c*HWc + (h0 + (p>>5))*Wc + w0 + (p&31)];
  }
  __syncthreads();

  const int p = t & 63, j = t >> 6;
  const int py = p >> 5, px = p & 31;

  u64p fp[16];
  #pragma unroll
  for (int c2 = 0; c2 < 16; c2++)
    fp[c2] = pk(fts[p*33 + 2*c2], fts[p*33 + 2*c2 + 1]);

  float acc[16];
  #pragma unroll
  for (int ch = 0; ch < 16; ch++) acc[ch] = 0.f;

  const float* wb = wss + j*49*32;
  const float* bb = bss + j*49;
  const float* xb = x1h + (j*16)*304 + py*38 + px;

  #pragma unroll 1
  for (int dy = 0; dy < 7; dy++) {
    #pragma unroll 1
    for (int dx = 0; dx < 7; dx++) {
      const int tt = dy*7 + dx;
      const float* wr2 = wb + tt*32;
      u64p k0 = 0ull, k1 = 0ull;
      #pragma unroll
      for (int c4 = 0; c4 < 8; c4++) {
        float4 wv = *(const float4*)&wr2[c4*4];
        fma2(k0, pk(wv.x, wv.y), fp[2*c4]);
        fma2(k1, pk(wv.z, wv.w), fp[2*c4 + 1]);
      }
      float2 ka = up(k0), kb = up(k1);
      const float kwt = bb[tt] + ((ka.x + ka.y) + (kb.x + kb.y));
      const float* src = xb + dy*38 + dx;
      #pragma unroll
      for (int ch = 0; ch < 16; ch++)
        acc[ch] += kwt * src[ch*304];
    }
  }

  float* gx2b = g_x2 + (b*64 + j*16)*HWc + (h0 + py)*Wc + (w0 + px);
  #pragma unroll
  for (int ch = 0; ch < 16; ch++) {
    float v = acc[ch];
    gx2b[ch*HWc] = (v >= 0.f) ? v : a2*v;
  }
}

// ---------------------------------------------------------------------------
// K3: psec 3x3 (32->32)+PReLU (R3 version). Tile 16x8, smem weights.
// ---------------------------------------------------------------------------
__global__ __launch_bounds__(256) void k_psec1(
    const float* __restrict__ wp1, const float* __restrict__ bp1,
    const float* __restrict__ app)
{
  extern __shared__ float sm[];
  float* fh  = sm;            // 32*180 = 5760
  float* wpt = fh + 5760;     // 9216 [ci*9+tap][oc]
  const int t = threadIdx.x;
  const int w0 = blockIdx.x << 4;
  const int h0 = blockIdx.y << 3;
  const int b  = blockIdx.z;
  const float ap = *app;

  const float* gfb = g_f + (b*32)*HWc;
  for (int i = t; i < 5760; i += 256) {
    int c = i / 180, r = i - c*180;
    int yy = r / 18, xx = r - yy*18;
    int gh = h0 - 1 + yy, gw = w0 - 1 + xx;
    float v = 0.f;
    if ((unsigned)gh < 128u && (unsigned)gw < 128u)
      v = gfb[c*HWc + gh*Wc + gw];
    fh[i] = v;
  }
  for (int i = t; i < 9216; i += 256) {
    int tc = i >> 5, o = i & 31;
    wpt[i] = wp1[o*288 + tc];
  }
  __syncthreads();

  const int oc0 = (t >> 6) * 8;
  const int pg  = t & 63;
  const int py  = pg >> 3;
  const int px0 = (pg & 7) * 2;

  u64p acc[4][2];
  #pragma unroll
  for (int o2 = 0; o2 < 4; o2++) {
    u64p bp = pk(bp1[oc0 + 2*o2], bp1[oc0 + 2*o2 + 1]);
    acc[o2][0] = bp; acc[o2][1] = bp;
  }

  #pragma unroll 1
  for (int ci = 0; ci < 32; ci++) {
    #pragma unroll
    for (int tap = 0; tap < 9; tap++) {
      const int di = tap / 3, dj = tap - di*3;
      ulonglong2 wa = *(const ulonglong2*)&wpt[(ci*9 + tap)*32 + oc0];
      ulonglong2 wbv = *(const ulonglong2*)&wpt[(ci*9 + tap)*32 + oc0 + 4];
      const float* fr = &fh[ci*180 + (py + di)*18 + px0 + dj];
      u64p xd0 = pk(fr[0], fr[0]), xd1 = pk(fr[1], fr[1]);
      fma2(acc[0][0], wa.x, xd0); fma2(acc[0][1], wa.x, xd1);
      fma2(acc[1][0], wa.y, xd0); fma2(acc[1][1], wa.y, xd1);
      fma2(acc[2][0], wbv.x, xd0); fma2(acc[2][1], wbv.x, xd1);
      fma2(acc[3][0], wbv.y, xd0); fma2(acc[3][1], wbv.y, xd1);
    }
  }

  float* ghb = g_h + (b*32)*HWc + (h0 + py)*Wc + (w0 + px0);
  #pragma unroll
  for (int o2 = 0; o2 < 4; o2++) {
    float2 v0 = up(acc[o2][0]);
    float2 v1 = up(acc[o2][1]);
    float a0 = (v0.x >= 0.f) ? v0.x : ap*v0.x;
    float b0 = (v0.y >= 0.f) ? v0.y : ap*v0.y;
    float a1v = (v1.x >= 0.f) ? v1.x : ap*v1.x;
    float b1v = (v1.y >= 0.f) ? v1.y : ap*v1.y;
    *(float2*)&ghb[(oc0 + 2*o2)*HWc]     = make_float2(a0, a1v);
    *(float2*)&ghb[(oc0 + 2*o2 + 1)*HWc] = make_float2(b0, b1v);
  }
}

// ---------------------------------------------------------------------------
// K4: HMMA final (R10 passing version).
// ---------------------------------------------------------------------------
#define PB 136
#define B_OFF 8448
#define SM4_BYTES (B_OFF + 304*PB*2)   // 91136

__global__ __launch_bounds__(256, 2) void k_final_mma(
    const float* __restrict__ wa, const float* __restrict__ ba,
    float* __restrict__ out)
{
  extern __shared__ char sm4[];
  const int t = threadIdx.x;
  const int wid = t >> 5, lane = t & 31;
  const int h = blockIdx.x & 127;
  const int b = blockIdx.x >> 7;
  float* attns = (float*)(sm4);
  float* was   = (float*)(sm4 + 512);
  float* zph   = (float*)(sm4 + 912);
  __nv_bfloat16* B = (__nv_bfloat16*)(sm4 + B_OFF);
  const uint32_t sbase = smem_u32(sm4);

  {
    const float* gzb = g_zp + (b*2)*HWc;
    for (int i = t; i < 1876; i += 256) {
      int c = i / 938, r = i - c*938;
      int yy = r / 134, xx = r - yy*134;
      int gh = h - 3 + yy, gw = xx - 3;
      float v = 0.f;
      if ((unsigned)gh < 128u && (unsigned)gw < 128u)
        v = gzb[c*HWc + gh*Wc + gw];
      zph[i] = v;
    }
    if (t < 98) was[t] = wa[t];
  }
  __syncthreads();

  if (t < 128) {
    float aacc = *ba;
    #pragma unroll
    for (int dy = 0; dy < 7; dy++)
      #pragma unroll
      for (int dx = 0; dx < 7; dx++) {
        const int o1 = dy*134 + t + dx;
        aacc += was[dy*7+dx]*zph[o1] + was[49 + dy*7+dx]*zph[938 + o1];
      }
    attns[t] = 1.f / (1.f + expf(-aacc));
  }
  __syncthreads();

  {
    const float* gx2b = g_x2 + (b*64)*HWc + h*Wc;
    for (int i = t; i < 4096; i += 256) {
      int c = i >> 6, n2 = (i & 63) * 2;
      float2 xv = *(const float2*)&gx2b[c*HWc + n2];
      float y0 = xv.x * attns[n2], y1 = xv.y * attns[n2+1];
      __nv_bfloat16 h0, l0, h1, l1; bf_split(y0, h0, l0); bf_split(y1, h1, l1);
      uint32_t hh = pk2bf(h0, h1), ll = pk2bf(l0, l1);
      *(uint32_t*)&B[c*PB + n2]         = hh;
      *(uint32_t*)&B[(64 + c)*PB + n2]  = hh;
      *(uint32_t*)&B[(128 + c)*PB + n2] = ll;
    }
    const float* ghb = g_h + (b*32)*HWc + h*Wc;
    for (int i = t; i < 2048; i += 256) {
      int c = i >> 6, n2 = (i & 63) * 2;
      float2 hv = *(const float2*)&ghb[c*HWc + n2];
      __nv_bfloat16 h0, l0, h1, l1; bf_split(hv.x, h0, l0); bf_split(hv.y, h1, l1);
      uint32_t hh = pk2bf(h0, h1), ll = pk2bf(l0, l1);
      *(uint32_t*)&B[(192 + c)*PB + n2] = hh;
      *(uint32_t*)&B[(224 + c)*PB + n2] = hh;
      *(uint32_t*)&B[(256 + c)*PB + n2] = ll;
    }
    if (t < 64) {
      int n2 = t*2;
      __nv_bfloat16 h0, l0, h1, l1;
      bf_split(attns[n2], h0, l0); bf_split(attns[n2+1], h1, l1);
      uint32_t hh = pk2bf(h0, h1), ll = pk2bf(l0, l1);
      *(uint32_t*)&B[288*PB + n2] = hh;
      *(uint32_t*)&B[289*PB + n2] = hh;
      *(uint32_t*)&B[290*PB + n2] = ll;
      __nv_bfloat16 one = __float2bfloat16(1.0f);
      uint32_t oo = pk2bf(one, one);
      *(uint32_t*)&B[291*PB + n2] = oo;
      *(uint32_t*)&B[292*PB + n2] = oo;
    }
    for (int i = t; i < 11*64; i += 256) {
      int r = 293 + (i >> 6), n2 = (i & 63) * 2;
      *(uint32_t*)&B[r*PB + n2] = 0u;
    }
  }
  __syncthreads();

  const int mw = wid & 3, nw = wid >> 2;
  const uint32_t Bbase = sbase + B_OFF;
  const uint4* __restrict__ afp = (const uint4*)g_afrag;

  float d[2][8][4];
  #pragma unroll
  for (int mt = 0; mt < 2; mt++)
    #pragma unroll
    for (int nt = 0; nt < 8; nt++)
      #pragma unroll
      for (int q = 0; q < 4; q++) d[mt][nt][q] = 0.f;

  uint4 a0 = afp[(0*8 + mw*2 + 0)*32 + lane];
  uint4 a1 = afp[(0*8 + mw*2 + 1)*32 + lane];

  #pragma unroll 1
  for (int kt = 0; kt < 19; kt++) {
    uint4 na0, na1;
    if (kt < 18) {
      na0 = afp[((kt+1)*8 + mw*2 + 0)*32 + lane];
      na1 = afp[((kt+1)*8 + mw*2 + 1)*32 + lane];
    }
    const uint32_t brow = Bbase + (uint32_t)(((kt*16 + (lane & 15))*PB + nw*64) * 2);
    #pragma unroll
    for (int nt = 0; nt < 8; nt++) {
      uint32_t bf[2];
      ldsm2t(bf, brow + nt*16);
      mma_bf16(d[0][nt], (const uint32_t*)&a0, bf);
      mma_bf16(d[1][nt], (const uint32_t*)&a1, bf);
    }
    a0 = na0; a1 = na1;
  }

  const int r = lane >> 2, c2 = (lane & 3) * 2;
  const int m_base = mw*32, n_base = nw*64;
  float* ob = out + (b*128)*HWc + h*Wc;
  #pragma unroll
  for (int mt = 0; mt < 2; mt++) {
    #pragma unroll
    for (int nt = 0; nt < 8; nt++) {
      const int m = m_base + mt*16 + r;
      const int n = n_base + nt*8 + c2;
      *(float2*)&ob[m*HWc + n]       = make_float2(d[mt][nt][0], d[mt][nt][1]);
      *(float2*)&ob[(m + 8)*HWc + n] = make_float2(d[mt][nt][2], d[mt][nt][3]);
    }
  }
}

// ---------------------------------------------------------------------------
extern "C" void kernel_launch(void* const* d_in, const int* in_sizes, int n_in,
                              void* d_out, int out_size)
{
  const float* x   = (const float*)d_in[0];
  const float* w1  = (const float*)d_in[1];
  const float* b1  = (const float*)d_in[2];
  const float* a1  = (const float*)d_in[3];
  const float* wr  = (const float*)d_in[4];
  const float* br  = (const float*)d_in[5];
  const float* ws  = (const float*)d_in[6];
  const float* bs  = (const float*)d_in[7];
  const float* a2  = (const float*)d_in[8];
  const float* w2  = (const float*)d_in[9];
  const float* b2  = (const float*)d_in[10];
  const float* wa  = (const float*)d_in[11];
  const float* ba  = (const float*)d_in[12];
  const float* wp1 = (const float*)d_in[13];
  const float* bp1 = (const float*)d_in[14];
  const float* ap  = (const float*)d_in[15];
  const float* wp2 = (const float*)d_in[16];
  const float* bp2 = (const float*)d_in[17];
  float* out = (float*)d_out;

  const int s2 = 28036 * 4;   // k_inv
  const int s3 = 14976 * 4;   // k_psec1

  cudaFuncSetAttribute(k_front_mma, cudaFuncAttributeMaxDynamicSharedMemorySize, SMF_BYTES);
  cudaFuncSetAttribute(k_inv,       cudaFuncAttributeMaxDynamicSharedMemorySize, s2);
  cudaFuncSetAttribute(k_psec1,     cudaFuncAttributeMaxDynamicSharedMemorySize, s3);
  cudaFuncSetAttribute(k_final_mma, cudaFuncAttributeMaxDynamicSharedMemorySize, SM4_BYTES);

  k_prep_afrag<<<139, 256>>>(w2, b2, wp2, bp2, w1, b1, wr, br);
  k_front_mma<<<dim3(128, 2, 2), 256, SMF_BYTES>>>(x, a1, out);
  k_inv  <<<dim3(4, 64, 2), 256, s2>>>(ws, bs, a2);
  k_psec1<<<dim3(8, 16, 2), 256, s3>>>(wp1, bp1, ap);
  k_final_mma<<<256, 256, SM4_BYTES>>>(wa, ba, out);
}

// round 14
// speedup vs baseline: 1.5046x; 1.0140x over previous
#include <cuda_runtime.h>
#include <cuda_bf16.h>
#include <math.h>
#include <cstdint>

#define Hc 128
#define Wc 128
#define HWc 16384

typedef unsigned long long u64p;

__device__ __forceinline__ u64p pk(float lo, float hi) {
  u64p r; asm("mov.b64 %0, {%1,%2};" : "=l"(r) : "f"(lo), "f"(hi)); return r;
}
__device__ __forceinline__ void fma2(u64p& a, u64p x, u64p y) {
  asm("fma.rn.f32x2 %0, %1, %2, %0;" : "+l"(a) : "l"(x), "l"(y));
}
__device__ __forceinline__ float2 up(u64p v) {
  float2 f; asm("mov.b64 {%0,%1}, %2;" : "=f"(f.x), "=f"(f.y) : "l"(v)); return f;
}
__device__ __forceinline__ uint32_t smem_u32(const void* p) {
  uint32_t a;
  asm("{ .reg .u64 t; cvta.to.shared.u64 t, %1; cvt.u32.u64 %0, t; }" : "=r"(a) : "l"(p));
  return a;
}

// activations scratch
__device__ float g_x1[2*64*HWc];
__device__ float g_f [2*32*HWc];
__device__ float g_zp[2*2*HWc];
__device__ float g_x2[2*64*HWc];
__device__ float g_h [2*32*HWc];
// Prebuilt A fragments (canonical m16n8k16 layout, bf16x2 words):
__device__ uint32_t g_afrag [19*8*32*4];   // final fused GEMM  (K'=304, M=128)
__device__ uint32_t g_afrag1[25*4*32*4];   // conv1   (K'=400, M=64)
__device__ uint32_t g_afrag2[13*2*32*4];   // reduce  (K'=208, M=32)

// ---------------------------------------------------------------------------
// common mma helpers
// ---------------------------------------------------------------------------
__device__ __forceinline__ void ldsm2t(uint32_t* r, uint32_t addr) {
  asm volatile("ldmatrix.sync.aligned.m8n8.x2.trans.shared.b16 {%0,%1}, [%2];"
    : "=r"(r[0]), "=r"(r[1]) : "r"(addr));
}
__device__ __forceinline__ void mma_bf16(float* d, const uint32_t* a, const uint32_t* bf) {
  asm volatile(
    "mma.sync.aligned.m16n8k16.row.col.f32.bf16.bf16.f32 "
    "{%0,%1,%2,%3}, {%4,%5,%6,%7}, {%8,%9}, {%0,%1,%2,%3};"
    : "+f"(d[0]), "+f"(d[1]), "+f"(d[2]), "+f"(d[3])
    : "r"(a[0]), "r"(a[1]), "r"(a[2]), "r"(a[3]), "r"(bf[0]), "r"(bf[1]));
}
__device__ __forceinline__ void bf_split(float w, __nv_bfloat16& hi, __nv_bfloat16& lo) {
  hi = __float2bfloat16(w);
  lo = __float2bfloat16(w - __bfloat162float(hi));
}
__device__ __forceinline__ uint32_t pk2bf(__nv_bfloat16 a, __nv_bfloat16 b) {
  return (uint32_t)__bfloat16_as_ushort(a) | ((uint32_t)__bfloat16_as_ushort(b) << 16);
}

// ---------------------------------------------------------------------------
// K-prep: build all A-fragment tables (same as R11 passing build).
// ---------------------------------------------------------------------------
__device__ __forceinline__ __nv_bfloat16 hi_or_lo(float v, bool lo) {
  __nv_bfloat16 hi = __float2bfloat16(v);
  if (!lo) return hi;
  return __float2bfloat16(v - __bfloat162float(hi));
}
__device__ __forceinline__ __nv_bfloat16 aval_fin(int m, int k,
    const float* w2, const float* b2, const float* wp2, const float* bp2)
{
  if      (k < 64)  return hi_or_lo(w2[m*64 + k], false);
  else if (k < 128) return hi_or_lo(w2[m*64 + k - 64], true);
  else if (k < 192) return hi_or_lo(w2[m*64 + k - 128], false);
  else if (k < 224) return hi_or_lo(wp2[m*32 + k - 192], false);
  else if (k < 256) return hi_or_lo(wp2[m*32 + k - 224], true);
  else if (k < 288) return hi_or_lo(wp2[m*32 + k - 256], false);
  else if (k == 288) return hi_or_lo(b2[m], false);
  else if (k == 289) return hi_or_lo(b2[m], true);
  else if (k == 290) return hi_or_lo(b2[m], false);
  else if (k == 291) return hi_or_lo(bp2[m], false);
  else if (k == 292) return hi_or_lo(bp2[m], true);
  return __float2bfloat16(0.f);
}
__device__ __forceinline__ __nv_bfloat16 aval_c1(int m, int k,
    const float* w1, const float* b1)
{
  if      (k < 128) return hi_or_lo(w1[m*128 + k], false);
  else if (k < 256) return hi_or_lo(w1[m*128 + k - 128], true);
  else if (k < 384) return hi_or_lo(w1[m*128 + k - 256], false);
  else if (k == 384) return hi_or_lo(b1[m], false);
  else if (k == 385) return hi_or_lo(b1[m], true);
  return __float2bfloat16(0.f);
}
__device__ __forceinline__ __nv_bfloat16 aval_rd(int m, int k,
    const float* wr, const float* br)
{
  if      (k < 64)  return hi_or_lo(wr[m*64 + k], false);
  else if (k < 128) return hi_or_lo(wr[m*64 + k - 64], true);
  else if (k < 192) return hi_or_lo(wr[m*64 + k - 128], false);
  else if (k == 192) return hi_or_lo(br[m], false);
  else if (k == 193) return hi_or_lo(br[m], true);
  return __float2bfloat16(0.f);
}

__global__ void k_prep_afrag(
    const float* __restrict__ w2,  const float* __restrict__ b2,
    const float* __restrict__ wp2, const float* __restrict__ bp2,
    const float* __restrict__ w1,  const float* __restrict__ b1,
    const float* __restrict__ wr,  const float* __restrict__ br)
{
  int idx = blockIdx.x*256 + threadIdx.x;
  if (idx < 19456) {
    int q = idx & 3, lane = (idx >> 2) & 31, mt = (idx >> 7) & 7, kt = idx >> 10;
    int m = mt*16 + (lane >> 2) + ((q & 1) << 3);
    int c = kt*16 + ((lane & 3) << 1) + ((q >> 1) << 3);
    g_afrag[idx] = pk2bf(aval_fin(m, c, w2, b2, wp2, bp2),
                         aval_fin(m, c+1, w2, b2, wp2, bp2));
    return;
  }
  idx -= 19456;
  if (idx < 12800) {
    int q = idx & 3, lane = (idx >> 2) & 31, mt = (idx >> 7) & 3, kt = idx >> 9;
    int m = mt*16 + (lane >> 2) + ((q & 1) << 3);
    int c = kt*16 + ((lane & 3) << 1) + ((q >> 1) << 3);
    g_afrag1[idx] = pk2bf(aval_c1(m, c, w1, b1), aval_c1(m, c+1, w1, b1));
    return;
  }
  idx -= 12800;
  if (idx < 3328) {
    int q = idx & 3, lane = (idx >> 2) & 31, mt = (idx >> 7) & 1, kt = idx >> 8;
    int m = mt*16 + (lane >> 2) + ((q & 1) << 3);
    int c = kt*16 + ((lane & 3) << 1) + ((q >> 1) << 3);
    g_afrag2[idx] = pk2bf(aval_rd(m, c, wr, br), aval_rd(m, c+1, wr, br));
  }
}

// ---------------------------------------------------------------------------
// K1 (HMMA, R11 passing version): half-row (64 px).
// ---------------------------------------------------------------------------
#define PB1 72
#define FS_OFF 0
#define B1F_OFF 8704
#define SMF_BYTES 66304

__global__ __launch_bounds__(256, 3) void k_front_mma(
    const float* __restrict__ x, const float* __restrict__ a1p,
    float* __restrict__ dummy)
{
  extern __shared__ char smf[];
  const int t = threadIdx.x;
  const int wid = t >> 5, lane = t & 31;
  const int h  = blockIdx.x;
  const int p0 = blockIdx.y * 64;
  const int b  = blockIdx.z;
  const float a1 = *a1p;
  float* fs = (float*)(smf + FS_OFF);
  __nv_bfloat16* B = (__nv_bfloat16*)(smf + B1F_OFF);
  const uint32_t Bbase = smem_u32(smf) + B1F_OFF;

  {
    const float* xb = x + (b*128)*HWc + h*Wc + p0;
    for (int i = t; i < 4096; i += 256) {
      int c = i >> 5, n2 = (i & 31) * 2;
      float2 xv = *(const float2*)&xb[c*HWc + n2];
      __nv_bfloat16 h0, l0, h1, l1; bf_split(xv.x, h0, l0); bf_split(xv.y, h1, l1);
      uint32_t hh = pk2bf(h0, h1), ll = pk2bf(l0, l1);
      *(uint32_t*)&B[c*PB1 + n2]         = hh;
      *(uint32_t*)&B[(128 + c)*PB1 + n2] = hh;
      *(uint32_t*)&B[(256 + c)*PB1 + n2] = ll;
    }
    __nv_bfloat16 one = __float2bfloat16(1.0f);
    uint32_t oo = pk2bf(one, one);
    for (int i = t; i < 512; i += 256) {
      int r = 384 + (i >> 5), n2 = (i & 31) * 2;
      *(uint32_t*)&B[r*PB1 + n2] = (r < 386) ? oo : 0u;
    }
  }
  __syncthreads();

  const int mw = wid & 3, nw = wid >> 2;
  const uint4* __restrict__ afp1 = (const uint4*)g_afrag1;
  float d[4][4];
  #pragma unroll
  for (int nt = 0; nt < 4; nt++)
    #pragma unroll
    for (int q = 0; q < 4; q++) d[nt][q] = 0.f;

  uint4 a0 = afp1[(0*4 + mw)*32 + lane];
  #pragma unroll 1
  for (int kt = 0; kt < 25; kt++) {
    uint4 na;
    if (kt < 24) na = afp1[((kt+1)*4 + mw)*32 + lane];
    const uint32_t brow = Bbase + (uint32_t)(((kt*16 + (lane & 15))*PB1 + nw*32) * 2);
    #pragma unroll
    for (int nt = 0; nt < 4; nt++) {
      uint32_t bf[2];
      ldsm2t(bf, brow + nt*16);
      mma_bf16(d[nt], (const uint32_t*)&a0, bf);
    }
    a0 = na;
  }
  __syncthreads();

  {
    const int r = lane >> 2, c2 = (lane & 3) * 2;
    float* gx1b = g_x1 + (b*64)*HWc + h*Wc + p0;
    #pragma unroll
    for (int nt = 0; nt < 4; nt++) {
      const int n = nw*32 + nt*8 + c2;
      #pragma unroll
      for (int half = 0; half < 2; half++) {
        const int m = mw*16 + r + half*8;
        float v0 = d[nt][half*2], v1 = d[nt][half*2 + 1];
        v0 = (v0 >= 0.f) ? v0 : a1*v0;
        v1 = (v1 >= 0.f) ? v1 : a1*v1;
        *(float2*)&gx1b[m*HWc + n] = make_float2(v0, v1);
        __nv_bfloat16 h0, l0, h1, l1; bf_split(v0, h0, l0); bf_split(v1, h1, l1);
        uint32_t hh = pk2bf(h0, h1), ll = pk2bf(l0, l1);
        *(uint32_t*)&B[m*PB1 + n]         = hh;
        *(uint32_t*)&B[(64 + m)*PB1 + n]  = hh;
        *(uint32_t*)&B[(128 + m)*PB1 + n] = ll;
      }
    }
    __nv_bfloat16 one = __float2bfloat16(1.0f);
    uint32_t oo = pk2bf(one, one);
    for (int i = t; i < 512; i += 256) {
      int rr = 192 + (i >> 5), n2 = (i & 31) * 2;
      *(uint32_t*)&B[rr*PB1 + n2] = (rr < 194) ? oo : 0u;
    }
  }
  __syncthreads();

  const int mw2 = wid & 1, nw2 = wid >> 1;
  const uint4* __restrict__ afp2 = (const uint4*)g_afrag2;
  float d2[2][4];
  #pragma unroll
  for (int nt = 0; nt < 2; nt++)
    #pragma unroll
    for (int q = 0; q < 4; q++) d2[nt][q] = 0.f;

  uint4 a2 = afp2[(0*2 + mw2)*32 + lane];
  #pragma unroll 1
  for (int kt = 0; kt < 13; kt++) {
    uint4 na;
    if (kt < 12) na = afp2[((kt+1)*2 + mw2)*32 + lane];
    const uint32_t brow = Bbase + (uint32_t)(((kt*16 + (lane & 15))*PB1 + nw2*16) * 2);
    #pragma unroll
    for (int nt = 0; nt < 2; nt++) {
      uint32_t bf[2];
      ldsm2t(bf, brow + nt*16);
      mma_bf16(d2[nt], (const uint32_t*)&a2, bf);
    }
    a2 = na;
  }

  {
    const int r = lane >> 2, c2 = (lane & 3) * 2;
    float* gfb = g_f + (b*32)*HWc + h*Wc + p0;
    #pragma unroll
    for (int nt = 0; nt < 2; nt++) {
      const int n = nw2*16 + nt*8 + c2;
      #pragma unroll
      for (int half = 0; half < 2; half++) {
        const int m = mw2*16 + r + half*8;
        float v0 = fmaxf(d2[nt][half*2], 0.f);
        float v1 = fmaxf(d2[nt][half*2 + 1], 0.f);
        *(float2*)&gfb[m*HWc + n] = make_float2(v0, v1);
        *(float2*)&fs[m*68 + n]   = make_float2(v0, v1);
      }
    }
  }
  __syncthreads();

  if (t < 64) {
    float mx = -1e30f, sum = 0.f;
    #pragma unroll
    for (int c = 0; c < 32; c++) {
      float v = fs[c*68 + t];
      mx = fmaxf(mx, v);
      sum += v;
    }
    g_zp[(b*2)*HWc + h*Wc + p0 + t]   = mx;
    g_zp[(b*2+1)*HWc + h*Wc + p0 + t] = sum * (1.f/32.f);
  }
}

// ---------------------------------------------------------------------------
// K2: involution, ch-paired x1 layout. Tile 32x2 px.
// x1h layout: [chp(32)][pix(8*38)][2] -> reduce uses LDS.64 + fma2.
// ---------------------------------------------------------------------------
__global__ __launch_bounds__(256, 2) void k_inv(
    const float* __restrict__ ws, const float* __restrict__ bs,
    const float* __restrict__ a2p)
{
  extern __shared__ float sm[];
  float* x1h = sm;                // 32 chp * 304 pix * 2 = 19456
  float* wss = x1h + 19456;       // 6272
  float* bss = wss + 6272;        // 196
  float* fts = bss + 196;         // 64*33
  const int t = threadIdx.x;
  const int w0 = blockIdx.x << 5;
  const int h0 = blockIdx.y << 1;
  const int b  = blockIdx.z;
  const float a2 = *a2p;

  const float* gx1b = g_x1 + (b*64)*HWc;
  for (int i = t; i < 19456; i += 256) {
    int ch = i / 304, r = i - ch*304;
    int yy = r / 38, xx = r - yy*38;
    int gh = h0 - 3 + yy, gw = w0 - 3 + xx;
    float v = 0.f;
    if ((unsigned)gh < 128u && (unsigned)gw < 128u)
      v = gx1b[ch*HWc + gh*Wc + gw];
    x1h[(ch >> 1)*608 + r*2 + (ch & 1)] = v;
  }
  for (int i = t; i < 6272; i += 256) wss[i] = ws[i];
  if (t < 196) bss[t] = bs[t];
  const float* gfb = g_f + (b*32)*HWc;
  for (int i = t; i < 2048; i += 256) {
    int c = i >> 6, p = i & 63;
    fts[p*33 + c] = gfb[c*HWc + (h0 + (p>>5))*Wc + w0 + (p&31)];
  }
  __syncthreads();

  const int p = t & 63, j = t >> 6;
  const int py = p >> 5, px = p & 31;

  u64p fp[16];
  #pragma unroll
  for (int c2 = 0; c2 < 16; c2++)
    fp[c2] = pk(fts[p*33 + 2*c2], fts[p*33 + 2*c2 + 1]);

  u64p acc2[8];
  #pragma unroll
  for (int chp = 0; chp < 8; chp++) acc2[chp] = 0ull;

  const float* wb = wss + j*49*32;
  const float* bb = bss + j*49;
  const float* xb = x1h + (j*8)*608 + (py*38 + px)*2;

  #pragma unroll 1
  for (int dy = 0; dy < 7; dy++) {
    #pragma unroll 1
    for (int dx = 0; dx < 7; dx++) {
      const int tt = dy*7 + dx;
      const float* wr2 = wb + tt*32;
      u64p k0 = 0ull, k1 = 0ull;
      #pragma unroll
      for (int c4 = 0; c4 < 8; c4++) {
        float4 wv = *(const float4*)&wr2[c4*4];
        fma2(k0, pk(wv.x, wv.y), fp[2*c4]);
        fma2(k1, pk(wv.z, wv.w), fp[2*c4 + 1]);
      }
      float2 ka = up(k0), kb = up(k1);
      const float kwt = bb[tt] + ((ka.x + ka.y) + (kb.x + kb.y));
      const u64p kd = pk(kwt, kwt);
      const float* src = xb + (dy*38 + dx)*2;
      #pragma unroll
      for (int chp = 0; chp < 8; chp++) {
        u64p v = *(const u64p*)&src[chp*608];
        fma2(acc2[chp], kd, v);
      }
    }
  }

  float* gx2b = g_x2 + (b*64 + j*16)*HWc + (h0 + py)*Wc + (w0 + px);
  #pragma unroll
  for (int chp = 0; chp < 8; chp++) {
    float2 v = up(acc2[chp]);
    float e = (v.x >= 0.f) ? v.x : a2*v.x;
    float o = (v.y >= 0.f) ? v.y : a2*v.y;
    gx2b[(2*chp)*HWc]     = e;
    gx2b[(2*chp + 1)*HWc] = o;
  }
}

// ---------------------------------------------------------------------------
// K3: psec 3x3 (32->32)+PReLU. Tile 16x8, 128 thr, thread = 8oc x 4px.
// f patch register-cached across the 9 taps; fh pitch 20 for alignment.
// ---------------------------------------------------------------------------
__global__ __launch_bounds__(128, 3) void k_psec1(
    const float* __restrict__ wp1, const float* __restrict__ bp1,
    const float* __restrict__ app)
{
  extern __shared__ float sm[];
  float* fh  = sm;            // 32ch * 10row * 20col = 6400
  float* wpt = fh + 6400;     // 9216 [ci*9+tap][oc]
  const int t = threadIdx.x;
  const int w0 = blockIdx.x << 4;   // 8 x-tiles of 16
  const int h0 = blockIdx.y << 3;   // 16 y-tiles of 8
  const int b  = blockIdx.z;
  const float ap = *app;

  const float* gfb = g_f + (b*32)*HWc;
  for (int i = t; i < 5760; i += 128) {
    int c = i / 180, r = i - c*180;
    int yy = r / 18, xx = r - yy*18;
    int gh = h0 - 1 + yy, gw = w0 - 1 + xx;
    float v = 0.f;
    if ((unsigned)gh < 128u && (unsigned)gw < 128u)
      v = gfb[c*HWc + gh*Wc + gw];
    fh[c*200 + yy*20 + xx] = v;
  }
  for (int i = t; i < 9216; i += 128) {
    int tc = i >> 5, o = i & 31;
    wpt[i] = wp1[o*288 + tc];
  }
  __syncthreads();

  const int oc0 = (t >> 5) * 8;        // 4 groups x 8 oc (warp = one group)
  const int pt  = t & 31;
  const int py  = pt >> 2;             // 0..7
  const int px0 = (pt & 3) * 4;        // 0,4,8,12

  u64p acc[4][4];                      // oc-pair x px
  #pragma unroll
  for (int o2 = 0; o2 < 4; o2++) {
    u64p bp = pk(bp1[oc0 + 2*o2], bp1[oc0 + 2*o2 + 1]);
    #pragma unroll
    for (int p = 0; p < 4; p++) acc[o2][p] = bp;
  }

  #pragma unroll 1
  for (int ci = 0; ci < 32; ci++) {
    // register-cache the 3x6 f patch for this channel
    float fc[3][6];
    #pragma unroll
    for (int jr = 0; jr < 3; jr++) {
      const float* fr = &fh[ci*200 + (py + jr)*20 + px0];
      float4 fa = *(const float4*)fr;
      float2 fb = *(const float2*)(fr + 4);
      fc[jr][0] = fa.x; fc[jr][1] = fa.y; fc[jr][2] = fa.z;
      fc[jr][3] = fa.w; fc[jr][4] = fb.x; fc[jr][5] = fb.y;
    }
    #pragma unroll
    for (int tap = 0; tap < 9; tap++) {
      const int di = tap / 3, dj = tap - di*3;
      ulonglong2 wa  = *(const ulonglong2*)&wpt[(ci*9 + tap)*32 + oc0];
      ulonglong2 wbv = *(const ulonglong2*)&wpt[(ci*9 + tap)*32 + oc0 + 4];
      u64p wd[4] = {wa.x, wa.y, wbv.x, wbv.y};
      #pragma unroll
      for (int p = 0; p < 4; p++) {
        float xv = fc[di][p + dj];
        u64p xd = pk(xv, xv);
        fma2(acc[0][p], wd[0], xd);
        fma2(acc[1][p], wd[1], xd);
        fma2(acc[2][p], wd[2], xd);
        fma2(acc[3][p], wd[3], xd);
      }
    }
  }

  float* ghb = g_h + (b*32)*HWc + (h0 + py)*Wc + (w0 + px0);
  #pragma unroll
  for (int o2 = 0; o2 < 4; o2++) {
    float ev[4], ov[4];
    #pragma unroll
    for (int p = 0; p < 4; p++) {
      float2 v = up(acc[o2][p]);
      ev[p] = (v.x >= 0.f) ? v.x : ap*v.x;
      ov[p] = (v.y >= 0.f) ? v.y : ap*v.y;
    }
    *(float4*)&ghb[(oc0 + 2*o2)*HWc]     = make_float4(ev[0], ev[1], ev[2], ev[3]);
    *(float4*)&ghb[(oc0 + 2*o2 + 1)*HWc] = make_float4(ov[0], ov[1], ov[2], ov[3]);
  }
}

// ---------------------------------------------------------------------------
// K4: HMMA final (R10/R11 passing version).
// ---------------------------------------------------------------------------
#define PB 136
#define B_OFF 8448
#define SM4_BYTES (B_OFF + 304*PB*2)   // 91136

__global__ __launch_bounds__(256, 2) void k_final_mma(
    const float* __restrict__ wa, const float* __restrict__ ba,
    float* __restrict__ out)
{
  extern __shared__ char sm4[];
  const int t = threadIdx.x;
  const int wid = t >> 5, lane = t & 31;
  const int h = blockIdx.x & 127;
  const int b = blockIdx.x >> 7;
  float* attns = (float*)(sm4);
  float* was   = (float*)(sm4 + 512);
  float* zph   = (float*)(sm4 + 912);
  __nv_bfloat16* B = (__nv_bfloat16*)(sm4 + B_OFF);
  const uint32_t sbase = smem_u32(sm4);

  {
    const float* gzb = g_zp + (b*2)*HWc;
    for (int i = t; i < 1876; i += 256) {
      int c = i / 938, r = i - c*938;
      int yy = r / 134, xx = r - yy*134;
      int gh = h - 3 + yy, gw = xx - 3;
      float v = 0.f;
      if ((unsigned)gh < 128u && (unsigned)gw < 128u)
        v = gzb[c*HWc + gh*Wc + gw];
      zph[i] = v;
    }
    if (t < 98) was[t] = wa[t];
  }
  __syncthreads();

  if (t < 128) {
    float aacc = *ba;
    #pragma unroll
    for (int dy = 0; dy < 7; dy++)
      #pragma unroll
      for (int dx = 0; dx < 7; dx++) {
        const int o1 = dy*134 + t + dx;
        aacc += was[dy*7+dx]*zph[o1] + was[49 + dy*7+dx]*zph[938 + o1];
      }
    attns[t] = 1.f / (1.f + expf(-aacc));
  }
  __syncthreads();

  {
    const float* gx2b = g_x2 + (b*64)*HWc + h*Wc;
    for (int i = t; i < 4096; i += 256) {
      int c = i >> 6, n2 = (i & 63) * 2;
      float2 xv = *(const float2*)&gx2b[c*HWc + n2];
      float y0 = xv.x * attns[n2], y1 = xv.y * attns[n2+1];
      __nv_bfloat16 h0, l0, h1, l1; bf_split(y0, h0, l0); bf_split(y1, h1, l1);
      uint32_t hh = pk2bf(h0, h1), ll = pk2bf(l0, l1);
      *(uint32_t*)&B[c*PB + n2]         = hh;
      *(uint32_t*)&B[(64 + c)*PB + n2]  = hh;
      *(uint32_t*)&B[(128 + c)*PB + n2] = ll;
    }
    const float* ghb = g_h + (b*32)*HWc + h*Wc;
    for (int i = t; i < 2048; i += 256) {
      int c = i >> 6, n2 = (i & 63) * 2;
      float2 hv = *(const float2*)&ghb[c*HWc + n2];
      __nv_bfloat16 h0, l0, h1, l1; bf_split(hv.x, h0, l0); bf_split(hv.y, h1, l1);
      uint32_t hh = pk2bf(h0, h1), ll = pk2bf(l0, l1);
      *(uint32_t*)&B[(192 + c)*PB + n2] = hh;
      *(uint32_t*)&B[(224 + c)*PB + n2] = hh;
      *(uint32_t*)&B[(256 + c)*PB + n2] = ll;
    }
    if (t < 64) {
      int n2 = t*2;
      __nv_bfloat16 h0, l0, h1, l1;
      bf_split(attns[n2], h0, l0); bf_split(attns[n2+1], h1, l1);
      uint32_t hh = pk2bf(h0, h1), ll = pk2bf(l0, l1);
      *(uint32_t*)&B[288*PB + n2] = hh;
      *(uint32_t*)&B[289*PB + n2] = hh;
      *(uint32_t*)&B[290*PB + n2] = ll;
      __nv_bfloat16 one = __float2bfloat16(1.0f);
      uint32_t oo = pk2bf(one, one);
      *(uint32_t*)&B[291*PB + n2] = oo;
      *(uint32_t*)&B[292*PB + n2] = oo;
    }
    for (int i = t; i < 11*64; i += 256) {
      int r = 293 + (i >> 6), n2 = (i & 63) * 2;
      *(uint32_t*)&B[r*PB + n2] = 0u;
    }
  }
  __syncthreads();

  const int mw = wid & 3, nw = wid >> 2;
  const uint32_t Bbase = sbase + B_OFF;
  const uint4* __restrict__ afp = (const uint4*)g_afrag;

  float d[2][8][4];
  #pragma unroll
  for (int mt = 0; mt < 2; mt++)
    #pragma unroll
    for (int nt = 0; nt < 8; nt++)
      #pragma unroll
      for (int q = 0; q < 4; q++) d[mt][nt][q] = 0.f;

  uint4 a0 = afp[(0*8 + mw*2 + 0)*32 + lane];
  uint4 a1 = afp[(0*8 + mw*2 + 1)*32 + lane];

  #pragma unroll 1
  for (int kt = 0; kt < 19; kt++) {
    uint4 na0, na1;
    if (kt < 18) {
      na0 = afp[((kt+1)*8 + mw*2 + 0)*32 + lane];
      na1 = afp[((kt+1)*8 + mw*2 + 1)*32 + lane];
    }
    const uint32_t brow = Bbase + (uint32_t)(((kt*16 + (lane & 15))*PB + nw*64) * 2);
    #pragma unroll
    for (int nt = 0; nt < 8; nt++) {
      uint32_t bf[2];
      ldsm2t(bf, brow + nt*16);
      mma_bf16(d[0][nt], (const uint32_t*)&a0, bf);
      mma_bf16(d[1][nt], (const uint32_t*)&a1, bf);
    }
    a0 = na0; a1 = na1;
  }

  const int r = lane >> 2, c2 = (lane & 3) * 2;
  const int m_base = mw*32, n_base = nw*64;
  float* ob = out + (b*128)*HWc + h*Wc;
  #pragma unroll
  for (int mt = 0; mt < 2; mt++) {
    #pragma unroll
    for (int nt = 0; nt < 8; nt++) {
      const int m = m_base + mt*16 + r;
      const int n = n_base + nt*8 + c2;
      *(float2*)&ob[m*HWc + n]       = make_float2(d[mt][nt][0], d[mt][nt][1]);
      *(float2*)&ob[(m + 8)*HWc + n] = make_float2(d[mt][nt][2], d[mt][nt][3]);
    }
  }
}

// ---------------------------------------------------------------------------
extern "C" void kernel_launch(void* const* d_in, const int* in_sizes, int n_in,
                              void* d_out, int out_size)
{
  const float* x   = (const float*)d_in[0];
  const float* w1  = (const float*)d_in[1];
  const float* b1  = (const float*)d_in[2];
  const float* a1  = (const float*)d_in[3];
  const float* wr  = (const float*)d_in[4];
  const float* br  = (const float*)d_in[5];
  const float* ws  = (const float*)d_in[6];
  const float* bs  = (const float*)d_in[7];
  const float* a2  = (const float*)d_in[8];
  const float* w2  = (const float*)d_in[9];
  const float* b2  = (const float*)d_in[10];
  const float* wa  = (const float*)d_in[11];
  const float* ba  = (const float*)d_in[12];
  const float* wp1 = (const float*)d_in[13];
  const float* bp1 = (const float*)d_in[14];
  const float* ap  = (const float*)d_in[15];
  const float* wp2 = (const float*)d_in[16];
  const float* bp2 = (const float*)d_in[17];
  float* out = (float*)d_out;

  const int s2 = 28036 * 4;   // k_inv
  const int s3 = 15616 * 4;   // k_psec1 (6400 + 9216)

  cudaFuncSetAttribute(k_front_mma, cudaFuncAttributeMaxDynamicSharedMemorySize, SMF_BYTES);
  cudaFuncSetAttribute(k_inv,       cudaFuncAttributeMaxDynamicSharedMemorySize, s2);
  cudaFuncSetAttribute(k_psec1,     cudaFuncAttributeMaxDynamicSharedMemorySize, s3);
  cudaFuncSetAttribute(k_final_mma, cudaFuncAttributeMaxDynamicSharedMemorySize, SM4_BYTES);

  k_prep_afrag<<<139, 256>>>(w2, b2, wp2, bp2, w1, b1, wr, br);
  k_front_mma<<<dim3(128, 2, 2), 256, SMF_BYTES>>>(x, a1, out);
  k_inv  <<<dim3(4, 64, 2), 256, s2>>>(ws, bs, a2);
  k_psec1<<<dim3(8, 16, 2), 128, s3>>>(wp1, bp1, ap);
  k_final_mma<<<256, 256, SM4_BYTES>>>(wa, ba, out);
}